// round 9
// baseline (speedup 1.0000x reference)
#include <cuda_runtime.h>
#include <cuda_fp16.h>
#include <mma.h>
#include <math.h>

using namespace nvcuda;

#define NC 50000
#define NG 2000
#define D  64
#define NE 1000000
#define NP 500000
#define W3 (1.0f/3.0f)
#define BN_EPS 1e-5f

#define NGB (NG/2)          // gene blocks (2 genes/block)
#define NCB (NC/4)          // cell blocks (4 cells/block), NC%4==0

// ---------------- scratch (static device globals) --------------------------
__device__ int   d_deg_src1[NC], d_deg_src2[NC];
__device__ int   d_deg_dst1[NG], d_deg_dst2[NG];
__device__ int   d_off_c1[NC], d_off_c2[NC];
__device__ int   d_off_g1[NG], d_off_g2[NG];
__device__ float d_cj1[NC], d_cj2[NC], d_ci1[NG], d_ci2[NG];
__device__ int   d_ctr[4];
__device__ int   d_rk1[NE], d_rk2[NE];          // packed: cell_rank | gene_rank<<16
__device__ int   d_csr_g1[NE], d_csr_g2[NE];    // cell ids grouped by gene
__device__ int   d_csr_c1[NE], d_csr_c2[NE];    // gene ids grouped by cell
// pre-scaled fp16 tables, 8 x uint4 per row (64 halves); +1 zero dummy row
__device__ uint4 d_s1a[(NC+1)*8], d_s2a[(NC+1)*8];
__device__ uint4 d_s1b[(NC+1)*8], d_s2b[(NC+1)*8];
__device__ uint4 d_sg1a[(NG+1)*8], d_sg2a[(NG+1)*8];
__device__ uint4 d_sg1b[(NG+1)*8], d_sg2b[(NG+1)*8];
__device__ float d_ih[NG*D];
__device__ float d_u1[NC*D],  d_u2[NC*D];
// fp16 decoder tables
__device__ uint4 d_ufh1[NC*8], d_ufh2[NC*8], d_ihh[NG*8];

// ---------------- setup -----------------------------------------------------
__global__ void zero_kernel() {
    int i = blockIdx.x * blockDim.x + threadIdx.x;
    if (i < NC) { d_deg_src1[i]=0; d_deg_src2[i]=0; }
    if (i < NG) { d_deg_dst1[i]=0; d_deg_dst2[i]=0; }
    if (i < 4)  d_ctr[i] = 0;
    if (i < 8) {
        uint4 z = make_uint4(0,0,0,0);
        d_s1a [NC*8 + i] = z; d_s2a [NC*8 + i] = z;
        d_s1b [NC*8 + i] = z; d_s2b [NC*8 + i] = z;
        d_sg1a[NG*8 + i] = z; d_sg2a[NG*8 + i] = z;
        d_sg1b[NG*8 + i] = z; d_sg2b[NG*8 + i] = z;
    }
}

// single atomic pass: counters + per-edge packed ranks (coalesced int4 stores)
__global__ void hist_kernel(const int4* __restrict__ s1, const int4* __restrict__ t1,
                            const int4* __restrict__ s2, const int4* __restrict__ t2) {
    int i = blockIdx.x * blockDim.x + threadIdx.x;
    if (i >= NE/4) return;
    int4 a = __ldg(&s1[i]), b = __ldg(&t1[i]);
    int4 c = __ldg(&s2[i]), e = __ldg(&t2[i]);
    int4 r;
    r.x = atomicAdd(&d_deg_src1[a.x],1) | (atomicAdd(&d_deg_dst1[b.x],1) << 16);
    r.y = atomicAdd(&d_deg_src1[a.y],1) | (atomicAdd(&d_deg_dst1[b.y],1) << 16);
    r.z = atomicAdd(&d_deg_src1[a.z],1) | (atomicAdd(&d_deg_dst1[b.z],1) << 16);
    r.w = atomicAdd(&d_deg_src1[a.w],1) | (atomicAdd(&d_deg_dst1[b.w],1) << 16);
    ((int4*)d_rk1)[i] = r;
    r.x = atomicAdd(&d_deg_src2[c.x],1) | (atomicAdd(&d_deg_dst2[e.x],1) << 16);
    r.y = atomicAdd(&d_deg_src2[c.y],1) | (atomicAdd(&d_deg_dst2[e.y],1) << 16);
    r.z = atomicAdd(&d_deg_src2[c.z],1) | (atomicAdd(&d_deg_dst2[e.z],1) << 16);
    r.w = atomicAdd(&d_deg_src2[c.w],1) | (atomicAdd(&d_deg_dst2[e.w],1) << 16);
    ((int4*)d_rk2)[i] = r;
}

__device__ __forceinline__ int warp_alloc(int v, int* ctr, int lane) {
    int x = v;
    #pragma unroll
    for (int d = 1; d < 32; d <<= 1) {
        int y = __shfl_up_sync(0xffffffffu, x, d);
        if (lane >= d) x += y;
    }
    int tot = __shfl_sync(0xffffffffu, x, 31);
    int base = 0;
    if (lane == 31) base = atomicAdd(ctr, tot);
    base = __shfl_sync(0xffffffffu, base, 31);
    return base + x - v;
}

__global__ void prep_kernel() {
    int i = blockIdx.x * blockDim.x + threadIdx.x;
    int lane = threadIdx.x & 31;
    int dg1 = (i < NC) ? d_deg_src1[i] : 0;
    int dg2 = (i < NC) ? d_deg_src2[i] : 0;
    int o1 = warp_alloc(dg1, &d_ctr[0], lane);
    int o2 = warp_alloc(dg2, &d_ctr[1], lane);
    if (i < NC) {
        d_cj1[i] = dg1 ? rsqrtf((float)dg1) : 0.f;
        d_cj2[i] = dg2 ? rsqrtf((float)dg2) : 0.f;
        d_off_c1[i] = o1;
        d_off_c2[i] = o2;
    }
    if (i - lane < NG) {
        int e1 = (i < NG) ? d_deg_dst1[i] : 0;
        int e2 = (i < NG) ? d_deg_dst2[i] : 0;
        int p1 = warp_alloc(e1, &d_ctr[2], lane);
        int p2 = warp_alloc(e2, &d_ctr[3], lane);
        if (i < NG) {
            d_ci1[i] = e1 ? rsqrtf((float)e1) : 0.f;
            d_ci2[i] = e2 ? rsqrtf((float)e2) : 0.f;
            d_off_g1[i] = p1;
            d_off_g2[i] = p2;
        }
    }
}

// atomic-free scatter (32-bit stores; u16 scattered stores = LTS RMW, slower)
__global__ void scatter_kernel(const int4* __restrict__ s1, const int4* __restrict__ t1,
                               const int4* __restrict__ s2, const int4* __restrict__ t2) {
    int i = blockIdx.x * blockDim.x + threadIdx.x;
    if (i >= NE/4) return;
    int4 a = __ldg(&s1[i]), b = __ldg(&t1[i]);
    int4 c = __ldg(&s2[i]), e = __ldg(&t2[i]);
    int4 r1 = __ldg(&((const int4*)d_rk1)[i]);
    int4 r2 = __ldg(&((const int4*)d_rk2)[i]);
    int sa[4] = {a.x,a.y,a.z,a.w}, ta[4] = {b.x,b.y,b.z,b.w};
    int sc[4] = {c.x,c.y,c.z,c.w}, tc[4] = {e.x,e.y,e.z,e.w};
    int k1[4] = {r1.x,r1.y,r1.z,r1.w}, k2[4] = {r2.x,r2.y,r2.z,r2.w};
    #pragma unroll
    for (int k = 0; k < 4; k++) {
        d_csr_c1[__ldg(&d_off_c1[sa[k]]) + (k1[k] & 0xffff)] = ta[k];
        d_csr_g1[__ldg(&d_off_g1[ta[k]]) + (k1[k] >> 16)]    = sa[k];
        d_csr_c2[__ldg(&d_off_c2[sc[k]]) + (k2[k] & 0xffff)] = tc[k];
        d_csr_g2[__ldg(&d_off_g2[tc[k]]) + (k2[k] >> 16)]    = sc[k];
    }
}

// init: fp32 accumulators + pre-scaled fp16 layer-0 tables
__global__ void scale_init_kernel(const float4* __restrict__ cf1,
                                  const float4* __restrict__ cf2,
                                  const float4* __restrict__ gf) {
    int i = blockIdx.x * blockDim.x + threadIdx.x;
    if (i < NC*16) {
        int row = i >> 4;
        float4 x1 = __ldg(&cf1[i]), x2 = __ldg(&cf2[i]);
        float w1 = __ldg(&d_cj1[row]), w2 = __ldg(&d_cj2[row]);
        ((float4*)d_u1)[i] = make_float4(W3*x1.x, W3*x1.y, W3*x1.z, W3*x1.w);
        ((float4*)d_u2)[i] = make_float4(W3*x2.x, W3*x2.y, W3*x2.z, W3*x2.w);
        ((__half2*)d_s1a)[2*i]   = __floats2half2_rn(w1*x1.x, w1*x1.y);
        ((__half2*)d_s1a)[2*i+1] = __floats2half2_rn(w1*x1.z, w1*x1.w);
        ((__half2*)d_s2a)[2*i]   = __floats2half2_rn(w2*x2.x, w2*x2.y);
        ((__half2*)d_s2a)[2*i+1] = __floats2half2_rn(w2*x2.z, w2*x2.w);
    }
    if (i < NG*16) {
        int row = i >> 4;
        float4 g = __ldg(&gf[i]);
        float w1 = __ldg(&d_ci1[row]), w2 = __ldg(&d_ci2[row]);
        ((float4*)d_ih)[i] = make_float4(W3*g.x, W3*g.y, W3*g.z, W3*g.w);
        ((__half2*)d_sg1a)[2*i]   = __floats2half2_rn(w1*g.x, w1*g.y);
        ((__half2*)d_sg1a)[2*i+1] = __floats2half2_rn(w1*g.z, w1*g.w);
        ((__half2*)d_sg2a)[2*i]   = __floats2half2_rn(w2*g.x, w2*g.y);
        ((__half2*)d_sg2a)[2*i+1] = __floats2half2_rn(w2*g.z, w2*g.w);
    }
}

// ---------------- gather: branch-free full batches + trimmed tail -----------
__device__ __forceinline__ void gather_rows4(const uint4* __restrict__ C,
                                             const int* __restrict__ csr,
                                             int beg, int cnt, int start, int step,
                                             int dummy, int lane, float* facc) {
    const int grp = lane >> 3, il = lane & 7;
    const __half2 z = __float2half2_rn(0.f);
    int base = start;
    // full batches: no bounds checks, 8 LDG.128 in flight
    for (; base + 32 <= cnt; base += step) {
        int idx = __ldg(&csr[beg + base + lane]);
        __half2 a[8];
        #pragma unroll
        for (int k = 0; k < 8; k++) a[k] = z;
        #pragma unroll
        for (int j = 0; j < 32; j += 8) {
            int bi = __shfl_sync(0xffffffffu, idx, j + grp);
            uint4 r = __ldg(&C[bi*8 + il]);
            const __half2* h = (const __half2*)&r;
            a[0] = __hadd2(a[0], h[0]); a[1] = __hadd2(a[1], h[1]);
            a[2] = __hadd2(a[2], h[2]); a[3] = __hadd2(a[3], h[3]);
            bi = __shfl_sync(0xffffffffu, idx, j + 4 + grp);
            r = __ldg(&C[bi*8 + il]);
            a[4] = __hadd2(a[4], h[0]); a[5] = __hadd2(a[5], h[1]);
            a[6] = __hadd2(a[6], h[2]); a[7] = __hadd2(a[7], h[3]);
        }
        #pragma unroll
        for (int k = 0; k < 8; k++) {
            float2 f = __half22float2(a[k]);
            facc[2*(k & 3)]     += f.x;
            facc[2*(k & 3) + 1] += f.y;
        }
    }
    // tail batch: only ceil(m/4) row-steps (dummy rows beyond m)
    if (base < cnt) {
        int p = base + lane;
        int idx = (p < cnt) ? __ldg(&csr[beg + p]) : dummy;
        int m = cnt - base;
        int mr = (m + 3) & ~3;
        __half2 a[8];
        #pragma unroll
        for (int k = 0; k < 8; k++) a[k] = z;
        for (int j = 0; j < mr; j += 8) {
            int bi = __shfl_sync(0xffffffffu, idx, j + grp);
            uint4 r = __ldg(&C[bi*8 + il]);
            const __half2* h = (const __half2*)&r;
            a[0] = __hadd2(a[0], h[0]); a[1] = __hadd2(a[1], h[1]);
            a[2] = __hadd2(a[2], h[2]); a[3] = __hadd2(a[3], h[3]);
            if (j + 4 < mr) {
                bi = __shfl_sync(0xffffffffu, idx, j + 4 + grp);
                uint4 r2 = __ldg(&C[bi*8 + il]);
                const __half2* h2 = (const __half2*)&r2;
                a[4] = __hadd2(a[4], h2[0]); a[5] = __hadd2(a[5], h2[1]);
                a[6] = __hadd2(a[6], h2[2]); a[7] = __hadd2(a[7], h2[3]);
            }
        }
        #pragma unroll
        for (int k = 0; k < 8; k++) {
            float2 f = __half22float2(a[k]);
            facc[2*(k & 3)]     += f.x;
            facc[2*(k & 3) + 1] += f.y;
        }
    }
    // reduce across the 4 groups
    #pragma unroll
    for (int k = 0; k < 8; k++) {
        facc[k] += __shfl_xor_sync(0xffffffffu, facc[k], 8);
        facc[k] += __shfl_xor_sync(0xffffffffu, facc[k], 16);
    }
}

// ---------------- fused per-layer SpMM --------------------------------------
__global__ void layer_kernel(int layer) {
    const int tid  = threadIdx.x;
    const int lane = tid & 31;
    const int il   = lane & 7;

    if (blockIdx.x < NGB) {
        const uint4* C1 = layer ? d_s1b : d_s1a;
        const uint4* C2 = layer ? d_s2b : d_s2a;
        const int gl   = tid >> 7;
        const int g    = blockIdx.x * 2 + gl;
        const int lw   = (tid >> 5) & 3;
        const int rel  = lw >> 1;
        const int half = lw & 1;

        const int*   csr = rel ? d_csr_g2 : d_csr_g1;
        const uint4* C   = rel ? C2       : C1;
        const int beg = rel ? d_off_g2[g]  : d_off_g1[g];
        const int cnt = rel ? d_deg_dst2[g]: d_deg_dst1[g];

        float facc[8] = {0,0,0,0,0,0,0,0};
        gather_rows4(C, csr, beg, cnt, half * 32, 64, NC, lane, facc);

        __shared__ float part[8][64];
        if (lane < 8) {
            #pragma unroll
            for (int k = 0; k < 8; k++) part[tid >> 5][il*8 + k] = facc[k];
        }
        __syncthreads();
        if ((tid & 127) < 64) {
            int d = tid & 63;
            float p0 = part[gl*4+0][d], p1 = part[gl*4+1][d];
            float p2 = part[gl*4+2][d], p3 = part[gl*4+3][d];
            float c1s = d_ci1[g], c2s = d_ci2[g];
            float go = 0.5f * (c1s * (p0 + p1) + c2s * (p2 + p3));
            float ih = d_ih[g*64 + d] + W3 * go;
            d_ih[g*64 + d] = ih;
            if (!layer) {
                ((__half*)d_sg1b)[g*64 + d] = __float2half(c1s * go);
                ((__half*)d_sg2b)[g*64 + d] = __float2half(c2s * go);
            } else {
                ((__half*)d_ihh)[g*64 + d] = __float2half(ih);
            }
        }
    } else {
        const uint4* G1 = layer ? d_sg1b : d_sg1a;
        const uint4* G2 = layer ? d_sg2b : d_sg2a;
        const int c   = (blockIdx.x - NGB) * 4 + (tid >> 6);
        const int rel = (tid >> 5) & 1;
        const int lane32 = tid & 31;

        const int*   csr = rel ? d_csr_c2 : d_csr_c1;
        const uint4* G   = rel ? G2       : G1;
        const int beg = rel ? d_off_c2[c]  : d_off_c1[c];
        const int cnt = rel ? d_deg_src2[c]: d_deg_src1[c];

        float facc[8] = {0,0,0,0,0,0,0,0};
        gather_rows4(G, csr, beg, cnt, 0, 32, NG, lane32, facc);

        if (lane32 < 8) {
            float s = rel ? d_cj2[c] : d_cj1[c];
            float v[8];
            #pragma unroll
            for (int k = 0; k < 8; k++) v[k] = s * facc[k];
            float* u = (rel ? d_u2 : d_u1) + c*64 + il*8;
            float4 u0 = ((float4*)u)[0], u1 = ((float4*)u)[1];
            u0.x += W3*v[0]; u0.y += W3*v[1]; u0.z += W3*v[2]; u0.w += W3*v[3];
            u1.x += W3*v[4]; u1.y += W3*v[5]; u1.z += W3*v[6]; u1.w += W3*v[7];
            ((float4*)u)[0] = u0; ((float4*)u)[1] = u1;
            if (!layer) {
                uint4 pk;
                __half2* ph = (__half2*)&pk;
                ph[0] = __floats2half2_rn(s*v[0], s*v[1]);
                ph[1] = __floats2half2_rn(s*v[2], s*v[3]);
                ph[2] = __floats2half2_rn(s*v[4], s*v[5]);
                ph[3] = __floats2half2_rn(s*v[6], s*v[7]);
                (rel ? d_s2b : d_s1b)[c*8 + il] = pk;
            }
        }
    }
}

// ---------------- embed via tensor cores (wmma m16n16k16) -------------------
// block = 128 threads (4 warps), 64 rows; grid = (ceil(NC/64), 2 branches).
// y = ELU((u @ W + beff) * scale + shift), output fp16 for the decoder.
__global__ void emb_kernel(const float* __restrict__ Wm, const float* __restrict__ bb,
                           const float* __restrict__ gam, const float* __restrict__ bet,
                           const float* __restrict__ mu,  const float* __restrict__ var) {
    const int branch = blockIdx.y;
    const float* __restrict__ U = branch ? d_u2 : d_u1;
    __half* __restrict__ UF     = branch ? (__half*)d_ufh2 : (__half*)d_ufh1;

    __shared__ __half sA[64][64];     // 8 KB: u rows fp16
    __shared__ __half sW[64][64];     // 8 KB: weights fp16
    __shared__ float  sC[4][16][64];  // 16 KB: per-warp C staging
    __shared__ float  sScale[64], sShift[64], sBeff[64];

    const int tid = threadIdx.x;
    const int row0 = blockIdx.x * 64;

    for (int t = tid; t < 4096; t += 128)
        sW[t >> 6][t & 63] = __float2half(Wm[t]);
    for (int t = tid; t < 4096; t += 128) {
        int r = t >> 6, k = t & 63;
        int gr = row0 + r;
        sA[r][k] = __float2half(gr < NC ? U[gr*64 + k] : 0.f);
    }
    if (tid < 64) {
        float sc = gam[tid] * rsqrtf(var[tid] + BN_EPS);
        sScale[tid] = sc;
        sShift[tid] = bet[tid] - mu[tid] * sc;
        sBeff[tid]  = bb[tid] + Wm[(64 + branch)*64 + tid];
    }
    __syncthreads();

    const int w = tid >> 5, lane = tid & 31;
    wmma::fragment<wmma::accumulator, 16, 16, 16, float> cf[4];
    #pragma unroll
    for (int n = 0; n < 4; n++) wmma::fill_fragment(cf[n], 0.f);
    #pragma unroll
    for (int k = 0; k < 4; k++) {
        wmma::fragment<wmma::matrix_a, 16, 16, 16, __half, wmma::row_major> af;
        wmma::load_matrix_sync(af, &sA[w*16][k*16], 64);
        #pragma unroll
        for (int n = 0; n < 4; n++) {
            wmma::fragment<wmma::matrix_b, 16, 16, 16, __half, wmma::row_major> bf;
            wmma::load_matrix_sync(bf, &sW[k*16][n*16], 64);
            wmma::mma_sync(cf[n], af, bf, cf[n]);
        }
    }
    #pragma unroll
    for (int n = 0; n < 4; n++)
        wmma::store_matrix_sync(&sC[w][0][n*16], cf[n], 64, wmma::mem_row_major);
    __syncwarp();

    for (int t = lane; t < 1024; t += 32) {
        int r = t >> 6, cc = t & 63;
        int gr = row0 + w*16 + r;
        if (gr < NC) {
            float y = (sC[w][r][cc] + sBeff[cc]) * sScale[cc] + sShift[cc];
            y = y > 0.f ? y : expm1f(y);
            UF[gr*64 + cc] = __float2half(y);
        }
    }
}

// ---------------- decoder: 8 lanes per edge, fp16 rows ----------------------
__global__ void dot_kernel(const int* __restrict__ ps1, const int* __restrict__ pd1,
                           const int* __restrict__ ps2, const int* __restrict__ pd2,
                           float* __restrict__ out) {
    int t = blockIdx.x * blockDim.x + threadIdx.x;
    int e = t >> 3;
    int l = t & 7;
    if (e >= 2*NP) return;
    const uint4* uf; int s, d;
    if (e < NP) { uf = d_ufh1; s = __ldg(&ps1[e]); d = __ldg(&pd1[e]); }
    else { int e2 = e - NP; uf = d_ufh2; s = __ldg(&ps2[e2]); d = __ldg(&pd2[e2]); }
    uint4 A = __ldg(&uf[s*8 + l]);
    uint4 B = __ldg(&d_ihh[d*8 + l]);
    const __half2* ha = (const __half2*)&A;
    const __half2* hb = (const __half2*)&B;
    float v = 0.f;
    #pragma unroll
    for (int k = 0; k < 4; k++) {
        float2 f = __half22float2(__hmul2(ha[k], hb[k]));
        v += f.x + f.y;
    }
    v += __shfl_xor_sync(0xffffffffu, v, 4);
    v += __shfl_xor_sync(0xffffffffu, v, 2);
    v += __shfl_xor_sync(0xffffffffu, v, 1);
    if (l == 0) out[e] = v;
}

// ---------------- host ------------------------------------------------------
extern "C" void kernel_launch(void* const* d_in, const int* in_sizes, int n_in,
                              void* d_out, int out_size) {
    const float* cf1 = (const float*)d_in[0];
    const float* cf2 = (const float*)d_in[1];
    const float* gf  = (const float*)d_in[2];
    const float* Wm  = (const float*)d_in[3];
    const float* bb  = (const float*)d_in[4];
    const float* gam = (const float*)d_in[5];
    const float* bet = (const float*)d_in[6];
    const float* mu  = (const float*)d_in[7];
    const float* var = (const float*)d_in[8];
    const int* es1 = (const int*)d_in[9];
    const int* ed1 = (const int*)d_in[10];
    const int* es2 = (const int*)d_in[11];
    const int* ed2 = (const int*)d_in[12];
    const int* ps1 = (const int*)d_in[13];
    const int* pd1 = (const int*)d_in[14];
    const int* ps2 = (const int*)d_in[15];
    const int* pd2 = (const int*)d_in[16];
    float* out = (float*)d_out;

    zero_kernel   <<<(NC + 255)/256, 256>>>();
    hist_kernel   <<<(NE/4 + 255)/256, 256>>>((const int4*)es1, (const int4*)ed1,
                                              (const int4*)es2, (const int4*)ed2);
    prep_kernel   <<<(NC + 255)/256, 256>>>();
    scatter_kernel<<<(NE/4 + 255)/256, 256>>>((const int4*)es1, (const int4*)ed1,
                                              (const int4*)es2, (const int4*)ed2);
    scale_init_kernel<<<(NC*16 + 255)/256, 256>>>((const float4*)cf1, (const float4*)cf2,
                                                  (const float4*)gf);

    layer_kernel<<<NGB + NCB, 256>>>(0);
    layer_kernel<<<NGB + NCB, 256>>>(1);

    emb_kernel<<<dim3((NC + 63)/64, 2), 128>>>(Wm, bb, gam, bet, mu, var);
    dot_kernel<<<(2*NP*8 + 255)/256, 256>>>(ps1, pd1, ps2, pd2, out);
}

// round 10
// speedup vs baseline: 1.1650x; 1.1650x over previous
#include <cuda_runtime.h>
#include <cuda_fp16.h>
#include <mma.h>
#include <math.h>

using namespace nvcuda;

#define NC 50000
#define NG 2000
#define D  64
#define NE 1000000
#define NP 500000
#define W3 (1.0f/3.0f)
#define BN_EPS 1e-5f

#define NGB (NG/2)          // gene blocks (2 genes/block)
#define NCB (NC/4)          // cell blocks (4 cells/block), NC%4==0

// ---------------- scratch (static device globals) --------------------------
__device__ int   d_deg_src1[NC], d_deg_src2[NC];
__device__ int   d_deg_dst1[NG], d_deg_dst2[NG];
__device__ int   d_off_c1[NC], d_off_c2[NC];
__device__ int   d_off_g1[NG], d_off_g2[NG];
__device__ float d_cj1[NC], d_cj2[NC], d_ci1[NG], d_ci2[NG];
__device__ int   d_ctr[4];
__device__ int   d_rk1[NE], d_rk2[NE];          // packed: cell_rank | gene_rank<<16
__device__ int   d_csr_g1[NE], d_csr_g2[NE];    // cell ids grouped by gene
__device__ int   d_csr_c1[NE], d_csr_c2[NE];    // gene ids grouped by cell
// pre-scaled fp16 tables, 8 x uint4 per row (64 halves); +1 zero dummy row
__device__ uint4 d_s1a[(NC+1)*8], d_s2a[(NC+1)*8];
__device__ uint4 d_s1b[(NC+1)*8], d_s2b[(NC+1)*8];
__device__ uint4 d_sg1a[(NG+1)*8], d_sg2a[(NG+1)*8];
__device__ uint4 d_sg1b[(NG+1)*8], d_sg2b[(NG+1)*8];
__device__ float d_ih[NG*D];
__device__ float d_u1[NC*D],  d_u2[NC*D];
// fp16 decoder tables
__device__ uint4 d_ufh1[NC*8], d_ufh2[NC*8], d_ihh[NG*8];

// ---------------- setup -----------------------------------------------------
__global__ void zero_kernel() {
    int i = blockIdx.x * blockDim.x + threadIdx.x;
    if (i < NC) { d_deg_src1[i]=0; d_deg_src2[i]=0; }
    if (i < NG) { d_deg_dst1[i]=0; d_deg_dst2[i]=0; }
    if (i < 4)  d_ctr[i] = 0;
    if (i < 8) {
        uint4 z = make_uint4(0,0,0,0);
        d_s1a [NC*8 + i] = z; d_s2a [NC*8 + i] = z;
        d_s1b [NC*8 + i] = z; d_s2b [NC*8 + i] = z;
        d_sg1a[NG*8 + i] = z; d_sg2a[NG*8 + i] = z;
        d_sg1b[NG*8 + i] = z; d_sg2b[NG*8 + i] = z;
    }
}

// single atomic pass: counters + per-edge packed ranks (coalesced int4 stores)
__global__ void hist_kernel(const int4* __restrict__ s1, const int4* __restrict__ t1,
                            const int4* __restrict__ s2, const int4* __restrict__ t2) {
    int i = blockIdx.x * blockDim.x + threadIdx.x;
    if (i >= NE/4) return;
    int4 a = __ldg(&s1[i]), b = __ldg(&t1[i]);
    int4 c = __ldg(&s2[i]), e = __ldg(&t2[i]);
    int4 r;
    r.x = atomicAdd(&d_deg_src1[a.x],1) | (atomicAdd(&d_deg_dst1[b.x],1) << 16);
    r.y = atomicAdd(&d_deg_src1[a.y],1) | (atomicAdd(&d_deg_dst1[b.y],1) << 16);
    r.z = atomicAdd(&d_deg_src1[a.z],1) | (atomicAdd(&d_deg_dst1[b.z],1) << 16);
    r.w = atomicAdd(&d_deg_src1[a.w],1) | (atomicAdd(&d_deg_dst1[b.w],1) << 16);
    ((int4*)d_rk1)[i] = r;
    r.x = atomicAdd(&d_deg_src2[c.x],1) | (atomicAdd(&d_deg_dst2[e.x],1) << 16);
    r.y = atomicAdd(&d_deg_src2[c.y],1) | (atomicAdd(&d_deg_dst2[e.y],1) << 16);
    r.z = atomicAdd(&d_deg_src2[c.z],1) | (atomicAdd(&d_deg_dst2[e.z],1) << 16);
    r.w = atomicAdd(&d_deg_src2[c.w],1) | (atomicAdd(&d_deg_dst2[e.w],1) << 16);
    ((int4*)d_rk2)[i] = r;
}

__device__ __forceinline__ int warp_alloc(int v, int* ctr, int lane) {
    int x = v;
    #pragma unroll
    for (int d = 1; d < 32; d <<= 1) {
        int y = __shfl_up_sync(0xffffffffu, x, d);
        if (lane >= d) x += y;
    }
    int tot = __shfl_sync(0xffffffffu, x, 31);
    int base = 0;
    if (lane == 31) base = atomicAdd(ctr, tot);
    base = __shfl_sync(0xffffffffu, base, 31);
    return base + x - v;
}

__global__ void prep_kernel() {
    int i = blockIdx.x * blockDim.x + threadIdx.x;
    int lane = threadIdx.x & 31;
    int dg1 = (i < NC) ? d_deg_src1[i] : 0;
    int dg2 = (i < NC) ? d_deg_src2[i] : 0;
    int o1 = warp_alloc(dg1, &d_ctr[0], lane);
    int o2 = warp_alloc(dg2, &d_ctr[1], lane);
    if (i < NC) {
        d_cj1[i] = dg1 ? rsqrtf((float)dg1) : 0.f;
        d_cj2[i] = dg2 ? rsqrtf((float)dg2) : 0.f;
        d_off_c1[i] = o1;
        d_off_c2[i] = o2;
    }
    if (i - lane < NG) {
        int e1 = (i < NG) ? d_deg_dst1[i] : 0;
        int e2 = (i < NG) ? d_deg_dst2[i] : 0;
        int p1 = warp_alloc(e1, &d_ctr[2], lane);
        int p2 = warp_alloc(e2, &d_ctr[3], lane);
        if (i < NG) {
            d_ci1[i] = e1 ? rsqrtf((float)e1) : 0.f;
            d_ci2[i] = e2 ? rsqrtf((float)e2) : 0.f;
            d_off_g1[i] = p1;
            d_off_g2[i] = p2;
        }
    }
}

// atomic-free scatter (32-bit stores; u16 scattered stores = LTS RMW, slower)
__global__ void scatter_kernel(const int4* __restrict__ s1, const int4* __restrict__ t1,
                               const int4* __restrict__ s2, const int4* __restrict__ t2) {
    int i = blockIdx.x * blockDim.x + threadIdx.x;
    if (i >= NE/4) return;
    int4 a = __ldg(&s1[i]), b = __ldg(&t1[i]);
    int4 c = __ldg(&s2[i]), e = __ldg(&t2[i]);
    int4 r1 = __ldg(&((const int4*)d_rk1)[i]);
    int4 r2 = __ldg(&((const int4*)d_rk2)[i]);
    int sa[4] = {a.x,a.y,a.z,a.w}, ta[4] = {b.x,b.y,b.z,b.w};
    int sc[4] = {c.x,c.y,c.z,c.w}, tc[4] = {e.x,e.y,e.z,e.w};
    int k1[4] = {r1.x,r1.y,r1.z,r1.w}, k2[4] = {r2.x,r2.y,r2.z,r2.w};
    #pragma unroll
    for (int k = 0; k < 4; k++) {
        d_csr_c1[__ldg(&d_off_c1[sa[k]]) + (k1[k] & 0xffff)] = ta[k];
        d_csr_g1[__ldg(&d_off_g1[ta[k]]) + (k1[k] >> 16)]    = sa[k];
        d_csr_c2[__ldg(&d_off_c2[sc[k]]) + (k2[k] & 0xffff)] = tc[k];
        d_csr_g2[__ldg(&d_off_g2[tc[k]]) + (k2[k] >> 16)]    = sc[k];
    }
}

// init: fp32 accumulators + pre-scaled fp16 layer-0 tables
__global__ void scale_init_kernel(const float4* __restrict__ cf1,
                                  const float4* __restrict__ cf2,
                                  const float4* __restrict__ gf) {
    int i = blockIdx.x * blockDim.x + threadIdx.x;
    if (i < NC*16) {
        int row = i >> 4;
        float4 x1 = __ldg(&cf1[i]), x2 = __ldg(&cf2[i]);
        float w1 = __ldg(&d_cj1[row]), w2 = __ldg(&d_cj2[row]);
        ((float4*)d_u1)[i] = make_float4(W3*x1.x, W3*x1.y, W3*x1.z, W3*x1.w);
        ((float4*)d_u2)[i] = make_float4(W3*x2.x, W3*x2.y, W3*x2.z, W3*x2.w);
        ((__half2*)d_s1a)[2*i]   = __floats2half2_rn(w1*x1.x, w1*x1.y);
        ((__half2*)d_s1a)[2*i+1] = __floats2half2_rn(w1*x1.z, w1*x1.w);
        ((__half2*)d_s2a)[2*i]   = __floats2half2_rn(w2*x2.x, w2*x2.y);
        ((__half2*)d_s2a)[2*i+1] = __floats2half2_rn(w2*x2.z, w2*x2.w);
    }
    if (i < NG*16) {
        int row = i >> 4;
        float4 g = __ldg(&gf[i]);
        float w1 = __ldg(&d_ci1[row]), w2 = __ldg(&d_ci2[row]);
        ((float4*)d_ih)[i] = make_float4(W3*g.x, W3*g.y, W3*g.z, W3*g.w);
        ((__half2*)d_sg1a)[2*i]   = __floats2half2_rn(w1*g.x, w1*g.y);
        ((__half2*)d_sg1a)[2*i+1] = __floats2half2_rn(w1*g.z, w1*g.w);
        ((__half2*)d_sg2a)[2*i]   = __floats2half2_rn(w2*g.x, w2*g.y);
        ((__half2*)d_sg2a)[2*i+1] = __floats2half2_rn(w2*g.z, w2*g.w);
    }
}

// ---------------- gather: R8-proven branch-free 32-row batches --------------
__device__ __forceinline__ void gather_rows4(const uint4* __restrict__ C,
                                             const int* __restrict__ csr,
                                             int beg, int cnt, int start, int step,
                                             int dummy, int lane, float* facc) {
    const int grp = lane >> 3, il = lane & 7;
    const __half2 z = __float2half2_rn(0.f);
    for (int base = start; base < cnt; base += step) {
        int p = base + lane;
        int idx = (p < cnt) ? __ldg(&csr[beg + p]) : dummy;
        __half2 a[8];
        #pragma unroll
        for (int k = 0; k < 8; k++) a[k] = z;
        #pragma unroll
        for (int j = 0; j < 32; j += 4) {
            int bi = __shfl_sync(0xffffffffu, idx, j + grp);
            uint4 r = __ldg(&C[bi*8 + il]);
            const __half2* h = (const __half2*)&r;
            const int q = j & 4;   // 0 or 4: alternate banks
            a[q+0] = __hadd2(a[q+0], h[0]);
            a[q+1] = __hadd2(a[q+1], h[1]);
            a[q+2] = __hadd2(a[q+2], h[2]);
            a[q+3] = __hadd2(a[q+3], h[3]);
        }
        #pragma unroll
        for (int k = 0; k < 8; k++) {
            float2 f = __half22float2(a[k]);
            facc[2*(k & 3)]     += f.x;
            facc[2*(k & 3) + 1] += f.y;
        }
    }
    #pragma unroll
    for (int k = 0; k < 8; k++) {
        facc[k] += __shfl_xor_sync(0xffffffffu, facc[k], 8);
        facc[k] += __shfl_xor_sync(0xffffffffu, facc[k], 16);
    }
}

// ---------------- fused per-layer SpMM --------------------------------------
__global__ void layer_kernel(int layer) {
    const int tid  = threadIdx.x;
    const int lane = tid & 31;
    const int il   = lane & 7;

    if (blockIdx.x < NGB) {
        const uint4* C1 = layer ? d_s1b : d_s1a;
        const uint4* C2 = layer ? d_s2b : d_s2a;
        const int gl   = tid >> 7;
        const int g    = blockIdx.x * 2 + gl;
        const int lw   = (tid >> 5) & 3;
        const int rel  = lw >> 1;
        const int half = lw & 1;

        const int*   csr = rel ? d_csr_g2 : d_csr_g1;
        const uint4* C   = rel ? C2       : C1;
        const int beg = rel ? d_off_g2[g]  : d_off_g1[g];
        const int cnt = rel ? d_deg_dst2[g]: d_deg_dst1[g];

        float facc[8] = {0,0,0,0,0,0,0,0};
        gather_rows4(C, csr, beg, cnt, half * 32, 64, NC, lane, facc);

        __shared__ float part[8][64];
        if (lane < 8) {
            #pragma unroll
            for (int k = 0; k < 8; k++) part[tid >> 5][il*8 + k] = facc[k];
        }
        __syncthreads();
        if ((tid & 127) < 64) {
            int d = tid & 63;
            float p0 = part[gl*4+0][d], p1 = part[gl*4+1][d];
            float p2 = part[gl*4+2][d], p3 = part[gl*4+3][d];
            float c1s = d_ci1[g], c2s = d_ci2[g];
            float go = 0.5f * (c1s * (p0 + p1) + c2s * (p2 + p3));
            float ih = d_ih[g*64 + d] + W3 * go;
            d_ih[g*64 + d] = ih;
            if (!layer) {
                ((__half*)d_sg1b)[g*64 + d] = __float2half(c1s * go);
                ((__half*)d_sg2b)[g*64 + d] = __float2half(c2s * go);
            } else {
                ((__half*)d_ihh)[g*64 + d] = __float2half(ih);
            }
        }
    } else {
        const uint4* G1 = layer ? d_sg1b : d_sg1a;
        const uint4* G2 = layer ? d_sg2b : d_sg2a;
        const int c   = (blockIdx.x - NGB) * 4 + (tid >> 6);
        const int rel = (tid >> 5) & 1;
        const int lane32 = tid & 31;

        const int*   csr = rel ? d_csr_c2 : d_csr_c1;
        const uint4* G   = rel ? G2       : G1;
        const int beg = rel ? d_off_c2[c]  : d_off_c1[c];
        const int cnt = rel ? d_deg_src2[c]: d_deg_src1[c];

        float facc[8] = {0,0,0,0,0,0,0,0};
        gather_rows4(G, csr, beg, cnt, 0, 32, NG, lane32, facc);

        if (lane32 < 8) {
            float s = rel ? d_cj2[c] : d_cj1[c];
            float v[8];
            #pragma unroll
            for (int k = 0; k < 8; k++) v[k] = s * facc[k];
            float* u = (rel ? d_u2 : d_u1) + c*64 + il*8;
            float4 u0 = ((float4*)u)[0], u1 = ((float4*)u)[1];
            u0.x += W3*v[0]; u0.y += W3*v[1]; u0.z += W3*v[2]; u0.w += W3*v[3];
            u1.x += W3*v[4]; u1.y += W3*v[5]; u1.z += W3*v[6]; u1.w += W3*v[7];
            ((float4*)u)[0] = u0; ((float4*)u)[1] = u1;
            if (!layer) {
                uint4 pk;
                __half2* ph = (__half2*)&pk;
                ph[0] = __floats2half2_rn(s*v[0], s*v[1]);
                ph[1] = __floats2half2_rn(s*v[2], s*v[3]);
                ph[2] = __floats2half2_rn(s*v[4], s*v[5]);
                ph[3] = __floats2half2_rn(s*v[6], s*v[7]);
                (rel ? d_s2b : d_s1b)[c*8 + il] = pk;
            }
        }
    }
}

// ---------------- embed via wmma v2 (padded smem, conflict-free) ------------
// block = 128 threads (4 warps), 64 rows; grid = (ceil(NC/64), 2 branches).
// y = ELU((u @ W + beff) * scale + shift), output fp16 for the decoder.
__global__ void emb_kernel(const float* __restrict__ Wm, const float* __restrict__ bb,
                           const float* __restrict__ gam, const float* __restrict__ bet,
                           const float* __restrict__ mu,  const float* __restrict__ var) {
    const int branch = blockIdx.y;
    const float* __restrict__ U = branch ? d_u2 : d_u1;
    __half* __restrict__ UF     = branch ? (__half*)d_ufh2 : (__half*)d_ufh1;

    __shared__ __half sA[64][72];     // padded: 144B rows, conflict-free ldmatrix
    __shared__ __half sW[64][72];
    __shared__ float  sC[4][16][68];  // padded C staging
    __shared__ float  sScale[64], sShift[64], sBeff[64];

    const int tid = threadIdx.x;
    const int row0 = blockIdx.x * 64;

    for (int t = tid; t < 4096; t += 128)
        sW[t >> 6][t & 63] = __float2half(Wm[t]);
    for (int t = tid; t < 4096; t += 128) {
        int r = t >> 6, k = t & 63;
        int gr = row0 + r;
        sA[r][k] = __float2half(gr < NC ? U[gr*64 + k] : 0.f);
    }
    if (tid < 64) {
        float sc = gam[tid] * rsqrtf(var[tid] + BN_EPS);
        sScale[tid] = sc;
        sShift[tid] = bet[tid] - mu[tid] * sc;
        sBeff[tid]  = bb[tid] + Wm[(64 + branch)*64 + tid];
    }
    __syncthreads();

    const int w = tid >> 5, lane = tid & 31;
    wmma::fragment<wmma::accumulator, 16, 16, 16, float> cf[4];
    #pragma unroll
    for (int n = 0; n < 4; n++) wmma::fill_fragment(cf[n], 0.f);
    #pragma unroll
    for (int k = 0; k < 4; k++) {
        wmma::fragment<wmma::matrix_a, 16, 16, 16, __half, wmma::row_major> af;
        wmma::load_matrix_sync(af, &sA[w*16][k*16], 72);
        #pragma unroll
        for (int n = 0; n < 4; n++) {
            wmma::fragment<wmma::matrix_b, 16, 16, 16, __half, wmma::row_major> bf;
            wmma::load_matrix_sync(bf, &sW[k*16][n*16], 72);
            wmma::mma_sync(cf[n], af, bf, cf[n]);
        }
    }
    #pragma unroll
    for (int n = 0; n < 4; n++)
        wmma::store_matrix_sync(&sC[w][0][n*16], cf[n], 68, wmma::mem_row_major);
    __syncwarp();

    for (int t = lane; t < 1024; t += 32) {
        int r = t >> 6, cc = t & 63;
        int gr = row0 + w*16 + r;
        if (gr < NC) {
            float y = (sC[w][r][cc] + sBeff[cc]) * sScale[cc] + sShift[cc];
            y = y > 0.f ? y : expm1f(y);
            UF[gr*64 + cc] = __float2half(y);
        }
    }
}

// ---------------- decoder: 8 lanes per edge, fp16 rows ----------------------
__global__ void dot_kernel(const int* __restrict__ ps1, const int* __restrict__ pd1,
                           const int* __restrict__ ps2, const int* __restrict__ pd2,
                           float* __restrict__ out) {
    int t = blockIdx.x * blockDim.x + threadIdx.x;
    int e = t >> 3;
    int l = t & 7;
    if (e >= 2*NP) return;
    const uint4* uf; int s, d;
    if (e < NP) { uf = d_ufh1; s = __ldg(&ps1[e]); d = __ldg(&pd1[e]); }
    else { int e2 = e - NP; uf = d_ufh2; s = __ldg(&ps2[e2]); d = __ldg(&pd2[e2]); }
    uint4 A = __ldg(&uf[s*8 + l]);
    uint4 B = __ldg(&d_ihh[d*8 + l]);
    const __half2* ha = (const __half2*)&A;
    const __half2* hb = (const __half2*)&B;
    float v = 0.f;
    #pragma unroll
    for (int k = 0; k < 4; k++) {
        float2 f = __half22float2(__hmul2(ha[k], hb[k]));
        v += f.x + f.y;
    }
    v += __shfl_xor_sync(0xffffffffu, v, 4);
    v += __shfl_xor_sync(0xffffffffu, v, 2);
    v += __shfl_xor_sync(0xffffffffu, v, 1);
    if (l == 0) out[e] = v;
}

// ---------------- host ------------------------------------------------------
extern "C" void kernel_launch(void* const* d_in, const int* in_sizes, int n_in,
                              void* d_out, int out_size) {
    const float* cf1 = (const float*)d_in[0];
    const float* cf2 = (const float*)d_in[1];
    const float* gf  = (const float*)d_in[2];
    const float* Wm  = (const float*)d_in[3];
    const float* bb  = (const float*)d_in[4];
    const float* gam = (const float*)d_in[5];
    const float* bet = (const float*)d_in[6];
    const float* mu  = (const float*)d_in[7];
    const float* var = (const float*)d_in[8];
    const int* es1 = (const int*)d_in[9];
    const int* ed1 = (const int*)d_in[10];
    const int* es2 = (const int*)d_in[11];
    const int* ed2 = (const int*)d_in[12];
    const int* ps1 = (const int*)d_in[13];
    const int* pd1 = (const int*)d_in[14];
    const int* ps2 = (const int*)d_in[15];
    const int* pd2 = (const int*)d_in[16];
    float* out = (float*)d_out;

    zero_kernel   <<<(NC + 255)/256, 256>>>();
    hist_kernel   <<<(NE/4 + 255)/256, 256>>>((const int4*)es1, (const int4*)ed1,
                                              (const int4*)es2, (const int4*)ed2);
    prep_kernel   <<<(NC + 255)/256, 256>>>();
    scatter_kernel<<<(NE/4 + 255)/256, 256>>>((const int4*)es1, (const int4*)ed1,
                                              (const int4*)es2, (const int4*)ed2);
    scale_init_kernel<<<(NC*16 + 255)/256, 256>>>((const float4*)cf1, (const float4*)cf2,
                                                  (const float4*)gf);

    layer_kernel<<<NGB + NCB, 256>>>(0);
    layer_kernel<<<NGB + NCB, 256>>>(1);

    emb_kernel<<<dim3((NC + 63)/64, 2), 128>>>(Wm, bb, gam, bet, mu, var);
    dot_kernel<<<(2*NP*8 + 255)/256, 256>>>(ps1, pd1, ps2, pd2, out);
}

// round 11
// speedup vs baseline: 1.1998x; 1.0300x over previous
#include <cuda_runtime.h>
#include <cuda_fp16.h>
#include <mma.h>
#include <math.h>

using namespace nvcuda;

#define NC 50000
#define NG 2000
#define D  64
#define NE 1000000
#define NP 500000
#define W3 (1.0f/3.0f)
#define BN_EPS 1e-5f

#define NGB (NG/2)          // gene blocks (2 genes/block)
#define NCB (NC/4)          // cell blocks (4 cells/block), NC%4==0
#define SCAT_B ((NE/4 + 255)/256)     // scatter blocks
#define INIT_B ((NC*16 + 255)/256)    // scale_init blocks

// ---------------- scratch (static device globals) --------------------------
__device__ int   d_deg_src1[NC], d_deg_src2[NC];
__device__ int   d_deg_dst1[NG], d_deg_dst2[NG];
__device__ int   d_off_c1[NC], d_off_c2[NC];
__device__ int   d_off_g1[NG], d_off_g2[NG];
__device__ float d_cj1[NC], d_cj2[NC], d_ci1[NG], d_ci2[NG];
__device__ int   d_ctr[4];
__device__ int   d_rk1[NE], d_rk2[NE];          // packed: cell_rank | gene_rank<<16
__device__ int   d_csr_g1[NE], d_csr_g2[NE];    // cell ids grouped by gene
__device__ int   d_csr_c1[NE], d_csr_c2[NE];    // gene ids grouped by cell
// pre-scaled fp16 tables, 8 x uint4 per row (64 halves); +1 zero dummy row
__device__ uint4 d_s1a[(NC+1)*8], d_s2a[(NC+1)*8];
__device__ uint4 d_s1b[(NC+1)*8], d_s2b[(NC+1)*8];
__device__ uint4 d_sg1a[(NG+1)*8], d_sg2a[(NG+1)*8];
__device__ uint4 d_sg1b[(NG+1)*8], d_sg2b[(NG+1)*8];
__device__ float d_ih[NG*D];
__device__ float d_u1[NC*D],  d_u2[NC*D];
// fp16 decoder tables
__device__ uint4 d_ufh1[NC*8], d_ufh2[NC*8], d_ihh[NG*8];

// ---------------- setup -----------------------------------------------------
__global__ void zero_kernel() {
    int i = blockIdx.x * blockDim.x + threadIdx.x;
    if (i < NC) { d_deg_src1[i]=0; d_deg_src2[i]=0; }
    if (i < NG) { d_deg_dst1[i]=0; d_deg_dst2[i]=0; }
    if (i < 4)  d_ctr[i] = 0;
    if (i < 8) {
        uint4 z = make_uint4(0,0,0,0);
        d_s1a [NC*8 + i] = z; d_s2a [NC*8 + i] = z;
        d_s1b [NC*8 + i] = z; d_s2b [NC*8 + i] = z;
        d_sg1a[NG*8 + i] = z; d_sg2a[NG*8 + i] = z;
        d_sg1b[NG*8 + i] = z; d_sg2b[NG*8 + i] = z;
    }
}

// single atomic pass: counters + per-edge packed ranks (coalesced int4 stores)
__global__ void hist_kernel(const int4* __restrict__ s1, const int4* __restrict__ t1,
                            const int4* __restrict__ s2, const int4* __restrict__ t2) {
    int i = blockIdx.x * blockDim.x + threadIdx.x;
    if (i >= NE/4) return;
    int4 a = __ldg(&s1[i]), b = __ldg(&t1[i]);
    int4 c = __ldg(&s2[i]), e = __ldg(&t2[i]);
    int4 r;
    r.x = atomicAdd(&d_deg_src1[a.x],1) | (atomicAdd(&d_deg_dst1[b.x],1) << 16);
    r.y = atomicAdd(&d_deg_src1[a.y],1) | (atomicAdd(&d_deg_dst1[b.y],1) << 16);
    r.z = atomicAdd(&d_deg_src1[a.z],1) | (atomicAdd(&d_deg_dst1[b.z],1) << 16);
    r.w = atomicAdd(&d_deg_src1[a.w],1) | (atomicAdd(&d_deg_dst1[b.w],1) << 16);
    ((int4*)d_rk1)[i] = r;
    r.x = atomicAdd(&d_deg_src2[c.x],1) | (atomicAdd(&d_deg_dst2[e.x],1) << 16);
    r.y = atomicAdd(&d_deg_src2[c.y],1) | (atomicAdd(&d_deg_dst2[e.y],1) << 16);
    r.z = atomicAdd(&d_deg_src2[c.z],1) | (atomicAdd(&d_deg_dst2[e.z],1) << 16);
    r.w = atomicAdd(&d_deg_src2[c.w],1) | (atomicAdd(&d_deg_dst2[e.w],1) << 16);
    ((int4*)d_rk2)[i] = r;
}

__device__ __forceinline__ int warp_alloc(int v, int* ctr, int lane) {
    int x = v;
    #pragma unroll
    for (int d = 1; d < 32; d <<= 1) {
        int y = __shfl_up_sync(0xffffffffu, x, d);
        if (lane >= d) x += y;
    }
    int tot = __shfl_sync(0xffffffffu, x, 31);
    int base = 0;
    if (lane == 31) base = atomicAdd(ctr, tot);
    base = __shfl_sync(0xffffffffu, base, 31);
    return base + x - v;
}

__global__ void prep_kernel() {
    int i = blockIdx.x * blockDim.x + threadIdx.x;
    int lane = threadIdx.x & 31;
    int dg1 = (i < NC) ? d_deg_src1[i] : 0;
    int dg2 = (i < NC) ? d_deg_src2[i] : 0;
    int o1 = warp_alloc(dg1, &d_ctr[0], lane);
    int o2 = warp_alloc(dg2, &d_ctr[1], lane);
    if (i < NC) {
        d_cj1[i] = dg1 ? rsqrtf((float)dg1) : 0.f;
        d_cj2[i] = dg2 ? rsqrtf((float)dg2) : 0.f;
        d_off_c1[i] = o1;
        d_off_c2[i] = o2;
    }
    if (i - lane < NG) {
        int e1 = (i < NG) ? d_deg_dst1[i] : 0;
        int e2 = (i < NG) ? d_deg_dst2[i] : 0;
        int p1 = warp_alloc(e1, &d_ctr[2], lane);
        int p2 = warp_alloc(e2, &d_ctr[3], lane);
        if (i < NG) {
            d_ci1[i] = e1 ? rsqrtf((float)e1) : 0.f;
            d_ci2[i] = e2 ? rsqrtf((float)e2) : 0.f;
            d_off_g1[i] = p1;
            d_off_g2[i] = p2;
        }
    }
}

// merged scatter (latency-bound) + scale_init (BW-bound): co-resident blocks
// overlap idle issue slots with streaming work.
__global__ void build_init_kernel(const int4* __restrict__ s1, const int4* __restrict__ t1,
                                  const int4* __restrict__ s2, const int4* __restrict__ t2,
                                  const float4* __restrict__ cf1,
                                  const float4* __restrict__ cf2,
                                  const float4* __restrict__ gf) {
    if (blockIdx.x < SCAT_B) {
        int i = blockIdx.x * blockDim.x + threadIdx.x;
        if (i >= NE/4) return;
        int4 a = __ldg(&s1[i]), b = __ldg(&t1[i]);
        int4 c = __ldg(&s2[i]), e = __ldg(&t2[i]);
        int4 r1 = __ldg(&((const int4*)d_rk1)[i]);
        int4 r2 = __ldg(&((const int4*)d_rk2)[i]);
        int sa[4] = {a.x,a.y,a.z,a.w}, ta[4] = {b.x,b.y,b.z,b.w};
        int sc[4] = {c.x,c.y,c.z,c.w}, tc[4] = {e.x,e.y,e.z,e.w};
        int k1[4] = {r1.x,r1.y,r1.z,r1.w}, k2[4] = {r2.x,r2.y,r2.z,r2.w};
        #pragma unroll
        for (int k = 0; k < 4; k++) {
            d_csr_c1[__ldg(&d_off_c1[sa[k]]) + (k1[k] & 0xffff)] = ta[k];
            d_csr_g1[__ldg(&d_off_g1[ta[k]]) + (k1[k] >> 16)]    = sa[k];
            d_csr_c2[__ldg(&d_off_c2[sc[k]]) + (k2[k] & 0xffff)] = tc[k];
            d_csr_g2[__ldg(&d_off_g2[tc[k]]) + (k2[k] >> 16)]    = sc[k];
        }
    } else {
        int i = (blockIdx.x - SCAT_B) * blockDim.x + threadIdx.x;
        if (i < NC*16) {
            int row = i >> 4;
            float4 x1 = __ldg(&cf1[i]), x2 = __ldg(&cf2[i]);
            float w1 = __ldg(&d_cj1[row]), w2 = __ldg(&d_cj2[row]);
            ((float4*)d_u1)[i] = make_float4(W3*x1.x, W3*x1.y, W3*x1.z, W3*x1.w);
            ((float4*)d_u2)[i] = make_float4(W3*x2.x, W3*x2.y, W3*x2.z, W3*x2.w);
            ((__half2*)d_s1a)[2*i]   = __floats2half2_rn(w1*x1.x, w1*x1.y);
            ((__half2*)d_s1a)[2*i+1] = __floats2half2_rn(w1*x1.z, w1*x1.w);
            ((__half2*)d_s2a)[2*i]   = __floats2half2_rn(w2*x2.x, w2*x2.y);
            ((__half2*)d_s2a)[2*i+1] = __floats2half2_rn(w2*x2.z, w2*x2.w);
        }
        if (i < NG*16) {
            int row = i >> 4;
            float4 g = __ldg(&gf[i]);
            float w1 = __ldg(&d_ci1[row]), w2 = __ldg(&d_ci2[row]);
            ((float4*)d_ih)[i] = make_float4(W3*g.x, W3*g.y, W3*g.z, W3*g.w);
            ((__half2*)d_sg1a)[2*i]   = __floats2half2_rn(w1*g.x, w1*g.y);
            ((__half2*)d_sg1a)[2*i+1] = __floats2half2_rn(w1*g.z, w1*g.w);
            ((__half2*)d_sg2a)[2*i]   = __floats2half2_rn(w2*g.x, w2*g.y);
            ((__half2*)d_sg2a)[2*i+1] = __floats2half2_rn(w2*g.z, w2*g.w);
        }
    }
}

// ---------------- gather: branch-free batches + index prefetch --------------
// Warp = 4 groups x 8 lanes; lane il loads uint4 #il of each 128B row.
// Next batch's index LDG issues BEFORE current batch's row loads, hiding the
// ~250cyc idx latency under row-gather latency.
__device__ __forceinline__ void gather_rows4(const uint4* __restrict__ C,
                                             const int* __restrict__ csr,
                                             int beg, int cnt, int start, int step,
                                             int dummy, int lane, float* facc) {
    const int grp = lane >> 3, il = lane & 7;
    const __half2 z = __float2half2_rn(0.f);
    int base = start;
    int p0 = base + lane;
    int idx = (p0 < cnt) ? __ldg(&csr[beg + p0]) : dummy;
    for (; base < cnt; base += step) {
        // prefetch next batch's index (independent of this batch's work)
        int nb = base + step;
        int np = nb + lane;
        int nidx = (nb < cnt && np < cnt) ? __ldg(&csr[beg + np]) : dummy;

        __half2 a[8];
        #pragma unroll
        for (int k = 0; k < 8; k++) a[k] = z;
        #pragma unroll
        for (int j = 0; j < 32; j += 4) {
            int bi = __shfl_sync(0xffffffffu, idx, j + grp);
            uint4 r = __ldg(&C[bi*8 + il]);
            const __half2* h = (const __half2*)&r;
            const int q = j & 4;   // 0 or 4: alternate banks
            a[q+0] = __hadd2(a[q+0], h[0]);
            a[q+1] = __hadd2(a[q+1], h[1]);
            a[q+2] = __hadd2(a[q+2], h[2]);
            a[q+3] = __hadd2(a[q+3], h[3]);
        }
        #pragma unroll
        for (int k = 0; k < 8; k++) {
            float2 f = __half22float2(a[k]);
            facc[2*(k & 3)]     += f.x;
            facc[2*(k & 3) + 1] += f.y;
        }
        idx = nidx;
    }
    #pragma unroll
    for (int k = 0; k < 8; k++) {
        facc[k] += __shfl_xor_sync(0xffffffffu, facc[k], 8);
        facc[k] += __shfl_xor_sync(0xffffffffu, facc[k], 16);
    }
}

// ---------------- fused per-layer SpMM --------------------------------------
__global__ void layer_kernel(int layer) {
    const int tid  = threadIdx.x;
    const int lane = tid & 31;
    const int il   = lane & 7;

    if (blockIdx.x < NGB) {
        const uint4* C1 = layer ? d_s1b : d_s1a;
        const uint4* C2 = layer ? d_s2b : d_s2a;
        const int gl   = tid >> 7;
        const int g    = blockIdx.x * 2 + gl;
        const int lw   = (tid >> 5) & 3;
        const int rel  = lw >> 1;
        const int half = lw & 1;

        const int*   csr = rel ? d_csr_g2 : d_csr_g1;
        const uint4* C   = rel ? C2       : C1;
        const int beg = rel ? d_off_g2[g]  : d_off_g1[g];
        const int cnt = rel ? d_deg_dst2[g]: d_deg_dst1[g];

        float facc[8] = {0,0,0,0,0,0,0,0};
        gather_rows4(C, csr, beg, cnt, half * 32, 64, NC, lane, facc);

        __shared__ float part[8][64];
        if (lane < 8) {
            #pragma unroll
            for (int k = 0; k < 8; k++) part[tid >> 5][il*8 + k] = facc[k];
        }
        __syncthreads();
        if ((tid & 127) < 64) {
            int d = tid & 63;
            float p0 = part[gl*4+0][d], p1 = part[gl*4+1][d];
            float p2 = part[gl*4+2][d], p3 = part[gl*4+3][d];
            float c1s = d_ci1[g], c2s = d_ci2[g];
            float go = 0.5f * (c1s * (p0 + p1) + c2s * (p2 + p3));
            float ih = d_ih[g*64 + d] + W3 * go;
            d_ih[g*64 + d] = ih;
            if (!layer) {
                ((__half*)d_sg1b)[g*64 + d] = __float2half(c1s * go);
                ((__half*)d_sg2b)[g*64 + d] = __float2half(c2s * go);
            } else {
                ((__half*)d_ihh)[g*64 + d] = __float2half(ih);
            }
        }
    } else {
        const uint4* G1 = layer ? d_sg1b : d_sg1a;
        const uint4* G2 = layer ? d_sg2b : d_sg2a;
        const int c   = (blockIdx.x - NGB) * 4 + (tid >> 6);
        const int rel = (tid >> 5) & 1;
        const int lane32 = tid & 31;

        const int*   csr = rel ? d_csr_c2 : d_csr_c1;
        const uint4* G   = rel ? G2       : G1;
        const int beg = rel ? d_off_c2[c]  : d_off_c1[c];
        const int cnt = rel ? d_deg_src2[c]: d_deg_src1[c];

        float facc[8] = {0,0,0,0,0,0,0,0};
        gather_rows4(G, csr, beg, cnt, 0, 32, NG, lane32, facc);

        if (lane32 < 8) {
            float s = rel ? d_cj2[c] : d_cj1[c];
            float v[8];
            #pragma unroll
            for (int k = 0; k < 8; k++) v[k] = s * facc[k];
            float* u = (rel ? d_u2 : d_u1) + c*64 + il*8;
            float4 u0 = ((float4*)u)[0], u1 = ((float4*)u)[1];
            u0.x += W3*v[0]; u0.y += W3*v[1]; u0.z += W3*v[2]; u0.w += W3*v[3];
            u1.x += W3*v[4]; u1.y += W3*v[5]; u1.z += W3*v[6]; u1.w += W3*v[7];
            ((float4*)u)[0] = u0; ((float4*)u)[1] = u1;
            if (!layer) {
                uint4 pk;
                __half2* ph = (__half2*)&pk;
                ph[0] = __floats2half2_rn(s*v[0], s*v[1]);
                ph[1] = __floats2half2_rn(s*v[2], s*v[3]);
                ph[2] = __floats2half2_rn(s*v[4], s*v[5]);
                ph[3] = __floats2half2_rn(s*v[6], s*v[7]);
                (rel ? d_s2b : d_s1b)[c*8 + il] = pk;
            }
        }
    }
}

// ---------------- embed via wmma (padded smem, conflict-free) ---------------
__global__ void emb_kernel(const float* __restrict__ Wm, const float* __restrict__ bb,
                           const float* __restrict__ gam, const float* __restrict__ bet,
                           const float* __restrict__ mu,  const float* __restrict__ var) {
    const int branch = blockIdx.y;
    const float* __restrict__ U = branch ? d_u2 : d_u1;
    __half* __restrict__ UF     = branch ? (__half*)d_ufh2 : (__half*)d_ufh1;

    __shared__ __half sA[64][72];
    __shared__ __half sW[64][72];
    __shared__ float  sC[4][16][68];
    __shared__ float  sScale[64], sShift[64], sBeff[64];

    const int tid = threadIdx.x;
    const int row0 = blockIdx.x * 64;

    for (int t = tid; t < 4096; t += 128)
        sW[t >> 6][t & 63] = __float2half(Wm[t]);
    for (int t = tid; t < 4096; t += 128) {
        int r = t >> 6, k = t & 63;
        int gr = row0 + r;
        sA[r][k] = __float2half(gr < NC ? U[gr*64 + k] : 0.f);
    }
    if (tid < 64) {
        float sc = gam[tid] * rsqrtf(var[tid] + BN_EPS);
        sScale[tid] = sc;
        sShift[tid] = bet[tid] - mu[tid] * sc;
        sBeff[tid]  = bb[tid] + Wm[(64 + branch)*64 + tid];
    }
    __syncthreads();

    const int w = tid >> 5, lane = tid & 31;
    wmma::fragment<wmma::accumulator, 16, 16, 16, float> cf[4];
    #pragma unroll
    for (int n = 0; n < 4; n++) wmma::fill_fragment(cf[n], 0.f);
    #pragma unroll
    for (int k = 0; k < 4; k++) {
        wmma::fragment<wmma::matrix_a, 16, 16, 16, __half, wmma::row_major> af;
        wmma::load_matrix_sync(af, &sA[w*16][k*16], 72);
        #pragma unroll
        for (int n = 0; n < 4; n++) {
            wmma::fragment<wmma::matrix_b, 16, 16, 16, __half, wmma::row_major> bf;
            wmma::load_matrix_sync(bf, &sW[k*16][n*16], 72);
            wmma::mma_sync(cf[n], af, bf, cf[n]);
        }
    }
    #pragma unroll
    for (int n = 0; n < 4; n++)
        wmma::store_matrix_sync(&sC[w][0][n*16], cf[n], 68, wmma::mem_row_major);
    __syncwarp();

    for (int t = lane; t < 1024; t += 32) {
        int r = t >> 6, cc = t & 63;
        int gr = row0 + w*16 + r;
        if (gr < NC) {
            float y = (sC[w][r][cc] + sBeff[cc]) * sScale[cc] + sShift[cc];
            y = y > 0.f ? y : expm1f(y);
            UF[gr*64 + cc] = __float2half(y);
        }
    }
}

// ---------------- decoder: 8 lanes per edge, fp16 rows ----------------------
__global__ void dot_kernel(const int* __restrict__ ps1, const int* __restrict__ pd1,
                           const int* __restrict__ ps2, const int* __restrict__ pd2,
                           float* __restrict__ out) {
    int t = blockIdx.x * blockDim.x + threadIdx.x;
    int e = t >> 3;
    int l = t & 7;
    if (e >= 2*NP) return;
    const uint4* uf; int s, d;
    if (e < NP) { uf = d_ufh1; s = __ldg(&ps1[e]); d = __ldg(&pd1[e]); }
    else { int e2 = e - NP; uf = d_ufh2; s = __ldg(&ps2[e2]); d = __ldg(&pd2[e2]); }
    uint4 A = __ldg(&uf[s*8 + l]);
    uint4 B = __ldg(&d_ihh[d*8 + l]);
    const __half2* ha = (const __half2*)&A;
    const __half2* hb = (const __half2*)&B;
    float v = 0.f;
    #pragma unroll
    for (int k = 0; k < 4; k++) {
        float2 f = __half22float2(__hmul2(ha[k], hb[k]));
        v += f.x + f.y;
    }
    v += __shfl_xor_sync(0xffffffffu, v, 4);
    v += __shfl_xor_sync(0xffffffffu, v, 2);
    v += __shfl_xor_sync(0xffffffffu, v, 1);
    if (l == 0) out[e] = v;
}

// ---------------- host ------------------------------------------------------
extern "C" void kernel_launch(void* const* d_in, const int* in_sizes, int n_in,
                              void* d_out, int out_size) {
    const float* cf1 = (const float*)d_in[0];
    const float* cf2 = (const float*)d_in[1];
    const float* gf  = (const float*)d_in[2];
    const float* Wm  = (const float*)d_in[3];
    const float* bb  = (const float*)d_in[4];
    const float* gam = (const float*)d_in[5];
    const float* bet = (const float*)d_in[6];
    const float* mu  = (const float*)d_in[7];
    const float* var = (const float*)d_in[8];
    const int* es1 = (const int*)d_in[9];
    const int* ed1 = (const int*)d_in[10];
    const int* es2 = (const int*)d_in[11];
    const int* ed2 = (const int*)d_in[12];
    const int* ps1 = (const int*)d_in[13];
    const int* pd1 = (const int*)d_in[14];
    const int* ps2 = (const int*)d_in[15];
    const int* pd2 = (const int*)d_in[16];
    float* out = (float*)d_out;

    zero_kernel<<<(NC + 255)/256, 256>>>();
    hist_kernel<<<(NE/4 + 255)/256, 256>>>((const int4*)es1, (const int4*)ed1,
                                           (const int4*)es2, (const int4*)ed2);
    prep_kernel<<<(NC + 255)/256, 256>>>();
    build_init_kernel<<<SCAT_B + INIT_B, 256>>>((const int4*)es1, (const int4*)ed1,
                                                (const int4*)es2, (const int4*)ed2,
                                                (const float4*)cf1, (const float4*)cf2,
                                                (const float4*)gf);

    layer_kernel<<<NGB + NCB, 256>>>(0);
    layer_kernel<<<NGB + NCB, 256>>>(1);

    emb_kernel<<<dim3((NC + 63)/64, 2), 128>>>(Wm, bb, gam, bet, mu, var);
    dot_kernel<<<(2*NP*8 + 255)/256, 256>>>(ps1, pd1, ps2, pd2, out);
}

// round 12
// speedup vs baseline: 1.3506x; 1.1256x over previous
#include <cuda_runtime.h>
#include <cuda_fp16.h>
#include <mma.h>
#include <math.h>

using namespace nvcuda;

#define NC 50000
#define NG 2000
#define D  64
#define NE 1000000
#define NP 500000
#define W3 (1.0f/3.0f)
#define BN_EPS 1e-5f

#define NGB (NG/2)          // gene blocks (2 genes/block)
#define NCB (NC/4)          // cell blocks (4 cells/block), NC%4==0
#define SCAT_B ((NE/4 + 255)/256)     // scatter blocks
#define INIT_B ((NC*16 + 255)/256)    // scale_init blocks

// ---------------- scratch (static device globals) --------------------------
__device__ int   d_deg_src1[NC], d_deg_src2[NC];
__device__ int   d_deg_dst1[NG], d_deg_dst2[NG];
__device__ int   d_dsh1[NG*8], d_dsh2[NG*8];    // 8-way sharded gene counters
__device__ int   d_goff1[NG*8], d_goff2[NG*8];  // per-shard CSR base offsets
__device__ int   d_off_c1[NC], d_off_c2[NC];
__device__ int   d_off_g1[NG], d_off_g2[NG];
__device__ float d_cj1[NC], d_cj2[NC], d_ci1[NG], d_ci2[NG];
__device__ int   d_ctr[4];
__device__ int   d_rk1[NE], d_rk2[NE];   // packed: cell_rank | ((g_rank<<3|shard)<<16)
__device__ int   d_csr_g1[NE], d_csr_g2[NE];    // cell ids grouped by gene
__device__ int   d_csr_c1[NE], d_csr_c2[NE];    // gene ids grouped by cell
// pre-scaled fp16 tables, 8 x uint4 per row (64 halves); +1 zero dummy row
__device__ uint4 d_s1a[(NC+1)*8], d_s2a[(NC+1)*8];
__device__ uint4 d_s1b[(NC+1)*8], d_s2b[(NC+1)*8];
__device__ uint4 d_sg1a[(NG+1)*8], d_sg2a[(NG+1)*8];
__device__ uint4 d_sg1b[(NG+1)*8], d_sg2b[(NG+1)*8];
__device__ float d_ih[NG*D];
__device__ float d_u1[NC*D],  d_u2[NC*D];
// fp16 decoder tables
__device__ uint4 d_ufh1[NC*8], d_ufh2[NC*8], d_ihh[NG*8];

// ---------------- setup -----------------------------------------------------
__global__ void zero_kernel() {
    int i = blockIdx.x * blockDim.x + threadIdx.x;
    if (i < NC) { d_deg_src1[i]=0; d_deg_src2[i]=0; }
    if (i < NG*8) { d_dsh1[i]=0; d_dsh2[i]=0; }
    if (i < 4)  d_ctr[i] = 0;
    if (i < 8) {
        uint4 z = make_uint4(0,0,0,0);
        d_s1a [NC*8 + i] = z; d_s2a [NC*8 + i] = z;
        d_s1b [NC*8 + i] = z; d_s2b [NC*8 + i] = z;
        d_sg1a[NG*8 + i] = z; d_sg2a[NG*8 + i] = z;
        d_sg1b[NG*8 + i] = z; d_sg2b[NG*8 + i] = z;
    }
}

// single atomic pass: cell counters (low contention) + 8-way sharded gene
// counters (contention/addr ÷8). rank packs: cell | ((g_rank<<3|shard)<<16).
__global__ void hist_kernel(const int4* __restrict__ s1, const int4* __restrict__ t1,
                            const int4* __restrict__ s2, const int4* __restrict__ t2) {
    int i = blockIdx.x * blockDim.x + threadIdx.x;
    if (i >= NE/4) return;
    const int sh = threadIdx.x & 7;
    int4 a = __ldg(&s1[i]), b = __ldg(&t1[i]);
    int4 c = __ldg(&s2[i]), e = __ldg(&t2[i]);
    int4 r;
    r.x = atomicAdd(&d_deg_src1[a.x],1) |
          ((unsigned)((atomicAdd(&d_dsh1[b.x*8+sh],1) << 3) | sh) << 16);
    r.y = atomicAdd(&d_deg_src1[a.y],1) |
          ((unsigned)((atomicAdd(&d_dsh1[b.y*8+sh],1) << 3) | sh) << 16);
    r.z = atomicAdd(&d_deg_src1[a.z],1) |
          ((unsigned)((atomicAdd(&d_dsh1[b.z*8+sh],1) << 3) | sh) << 16);
    r.w = atomicAdd(&d_deg_src1[a.w],1) |
          ((unsigned)((atomicAdd(&d_dsh1[b.w*8+sh],1) << 3) | sh) << 16);
    ((int4*)d_rk1)[i] = r;
    r.x = atomicAdd(&d_deg_src2[c.x],1) |
          ((unsigned)((atomicAdd(&d_dsh2[e.x*8+sh],1) << 3) | sh) << 16);
    r.y = atomicAdd(&d_deg_src2[c.y],1) |
          ((unsigned)((atomicAdd(&d_dsh2[e.y*8+sh],1) << 3) | sh) << 16);
    r.z = atomicAdd(&d_deg_src2[c.z],1) |
          ((unsigned)((atomicAdd(&d_dsh2[e.z*8+sh],1) << 3) | sh) << 16);
    r.w = atomicAdd(&d_deg_src2[c.w],1) |
          ((unsigned)((atomicAdd(&d_dsh2[e.w*8+sh],1) << 3) | sh) << 16);
    ((int4*)d_rk2)[i] = r;
}

__device__ __forceinline__ int warp_alloc(int v, int* ctr, int lane) {
    int x = v;
    #pragma unroll
    for (int d = 1; d < 32; d <<= 1) {
        int y = __shfl_up_sync(0xffffffffu, x, d);
        if (lane >= d) x += y;
    }
    int tot = __shfl_sync(0xffffffffu, x, 31);
    int base = 0;
    if (lane == 31) base = atomicAdd(ctr, tot);
    base = __shfl_sync(0xffffffffu, base, 31);
    return base + x - v;
}

__global__ void prep_kernel() {
    int i = blockIdx.x * blockDim.x + threadIdx.x;
    int lane = threadIdx.x & 31;
    int dg1 = (i < NC) ? d_deg_src1[i] : 0;
    int dg2 = (i < NC) ? d_deg_src2[i] : 0;
    int o1 = warp_alloc(dg1, &d_ctr[0], lane);
    int o2 = warp_alloc(dg2, &d_ctr[1], lane);
    if (i < NC) {
        d_cj1[i] = dg1 ? rsqrtf((float)dg1) : 0.f;
        d_cj2[i] = dg2 ? rsqrtf((float)dg2) : 0.f;
        d_off_c1[i] = o1;
        d_off_c2[i] = o2;
    }
    if (i - lane < NG) {
        int c1[8], c2[8];
        int e1 = 0, e2 = 0;
        if (i < NG) {
            int4 q;
            q = *(const int4*)&d_dsh1[i*8];   c1[0]=q.x; c1[1]=q.y; c1[2]=q.z; c1[3]=q.w;
            q = *(const int4*)&d_dsh1[i*8+4]; c1[4]=q.x; c1[5]=q.y; c1[6]=q.z; c1[7]=q.w;
            q = *(const int4*)&d_dsh2[i*8];   c2[0]=q.x; c2[1]=q.y; c2[2]=q.z; c2[3]=q.w;
            q = *(const int4*)&d_dsh2[i*8+4]; c2[4]=q.x; c2[5]=q.y; c2[6]=q.z; c2[7]=q.w;
            #pragma unroll
            for (int k = 0; k < 8; k++) { e1 += c1[k]; e2 += c2[k]; }
        }
        int p1 = warp_alloc(e1, &d_ctr[2], lane);
        int p2 = warp_alloc(e2, &d_ctr[3], lane);
        if (i < NG) {
            d_ci1[i] = e1 ? rsqrtf((float)e1) : 0.f;
            d_ci2[i] = e2 ? rsqrtf((float)e2) : 0.f;
            d_off_g1[i] = p1;  d_deg_dst1[i] = e1;
            d_off_g2[i] = p2;  d_deg_dst2[i] = e2;
            int run1 = p1, run2 = p2;
            #pragma unroll
            for (int k = 0; k < 8; k++) {
                d_goff1[i*8 + k] = run1; run1 += c1[k];
                d_goff2[i*8 + k] = run2; run2 += c2[k];
            }
        }
    }
}

// merged scatter (latency-bound) + scale_init (BW-bound)
__global__ void build_init_kernel(const int4* __restrict__ s1, const int4* __restrict__ t1,
                                  const int4* __restrict__ s2, const int4* __restrict__ t2,
                                  const float4* __restrict__ cf1,
                                  const float4* __restrict__ cf2,
                                  const float4* __restrict__ gf) {
    if (blockIdx.x < SCAT_B) {
        int i = blockIdx.x * blockDim.x + threadIdx.x;
        if (i >= NE/4) return;
        int4 a = __ldg(&s1[i]), b = __ldg(&t1[i]);
        int4 c = __ldg(&s2[i]), e = __ldg(&t2[i]);
        int4 r1 = __ldg(&((const int4*)d_rk1)[i]);
        int4 r2 = __ldg(&((const int4*)d_rk2)[i]);
        int sa[4] = {a.x,a.y,a.z,a.w}, ta[4] = {b.x,b.y,b.z,b.w};
        int sc[4] = {c.x,c.y,c.z,c.w}, tc[4] = {e.x,e.y,e.z,e.w};
        int k1[4] = {r1.x,r1.y,r1.z,r1.w}, k2[4] = {r2.x,r2.y,r2.z,r2.w};
        #pragma unroll
        for (int k = 0; k < 4; k++) {
            d_csr_c1[__ldg(&d_off_c1[sa[k]]) + (k1[k] & 0xffff)] = ta[k];
            unsigned gf1 = ((unsigned)k1[k]) >> 16;
            d_csr_g1[__ldg(&d_goff1[ta[k]*8 + (gf1 & 7)]) + (gf1 >> 3)] = sa[k];
            d_csr_c2[__ldg(&d_off_c2[sc[k]]) + (k2[k] & 0xffff)] = tc[k];
            unsigned gf2 = ((unsigned)k2[k]) >> 16;
            d_csr_g2[__ldg(&d_goff2[tc[k]*8 + (gf2 & 7)]) + (gf2 >> 3)] = sc[k];
        }
    } else {
        int i = (blockIdx.x - SCAT_B) * blockDim.x + threadIdx.x;
        if (i < NC*16) {
            int row = i >> 4;
            float4 x1 = __ldg(&cf1[i]), x2 = __ldg(&cf2[i]);
            float w1 = __ldg(&d_cj1[row]), w2 = __ldg(&d_cj2[row]);
            ((float4*)d_u1)[i] = make_float4(W3*x1.x, W3*x1.y, W3*x1.z, W3*x1.w);
            ((float4*)d_u2)[i] = make_float4(W3*x2.x, W3*x2.y, W3*x2.z, W3*x2.w);
            ((__half2*)d_s1a)[2*i]   = __floats2half2_rn(w1*x1.x, w1*x1.y);
            ((__half2*)d_s1a)[2*i+1] = __floats2half2_rn(w1*x1.z, w1*x1.w);
            ((__half2*)d_s2a)[2*i]   = __floats2half2_rn(w2*x2.x, w2*x2.y);
            ((__half2*)d_s2a)[2*i+1] = __floats2half2_rn(w2*x2.z, w2*x2.w);
        }
        if (i < NG*16) {
            int row = i >> 4;
            float4 g = __ldg(&gf[i]);
            float w1 = __ldg(&d_ci1[row]), w2 = __ldg(&d_ci2[row]);
            ((float4*)d_ih)[i] = make_float4(W3*g.x, W3*g.y, W3*g.z, W3*g.w);
            ((__half2*)d_sg1a)[2*i]   = __floats2half2_rn(w1*g.x, w1*g.y);
            ((__half2*)d_sg1a)[2*i+1] = __floats2half2_rn(w1*g.z, w1*g.w);
            ((__half2*)d_sg2a)[2*i]   = __floats2half2_rn(w2*g.x, w2*g.y);
            ((__half2*)d_sg2a)[2*i+1] = __floats2half2_rn(w2*g.z, w2*g.w);
        }
    }
}

// ---------------- gather: branch-free batches + index prefetch --------------
__device__ __forceinline__ void gather_rows4(const uint4* __restrict__ C,
                                             const int* __restrict__ csr,
                                             int beg, int cnt, int start, int step,
                                             int dummy, int lane, float* facc) {
    const int grp = lane >> 3, il = lane & 7;
    const __half2 z = __float2half2_rn(0.f);
    int base = start;
    int p0 = base + lane;
    int idx = (p0 < cnt) ? __ldg(&csr[beg + p0]) : dummy;
    for (; base < cnt; base += step) {
        int nb = base + step;
        int np = nb + lane;
        int nidx = (nb < cnt && np < cnt) ? __ldg(&csr[beg + np]) : dummy;

        __half2 a[8];
        #pragma unroll
        for (int k = 0; k < 8; k++) a[k] = z;
        #pragma unroll
        for (int j = 0; j < 32; j += 4) {
            int bi = __shfl_sync(0xffffffffu, idx, j + grp);
            uint4 r = __ldg(&C[bi*8 + il]);
            const __half2* h = (const __half2*)&r;
            const int q = j & 4;
            a[q+0] = __hadd2(a[q+0], h[0]);
            a[q+1] = __hadd2(a[q+1], h[1]);
            a[q+2] = __hadd2(a[q+2], h[2]);
            a[q+3] = __hadd2(a[q+3], h[3]);
        }
        #pragma unroll
        for (int k = 0; k < 8; k++) {
            float2 f = __half22float2(a[k]);
            facc[2*(k & 3)]     += f.x;
            facc[2*(k & 3) + 1] += f.y;
        }
        idx = nidx;
    }
    #pragma unroll
    for (int k = 0; k < 8; k++) {
        facc[k] += __shfl_xor_sync(0xffffffffu, facc[k], 8);
        facc[k] += __shfl_xor_sync(0xffffffffu, facc[k], 16);
    }
}

// ---------------- fused per-layer SpMM --------------------------------------
__global__ void layer_kernel(int layer) {
    const int tid  = threadIdx.x;
    const int lane = tid & 31;
    const int il   = lane & 7;

    if (blockIdx.x < NGB) {
        const uint4* C1 = layer ? d_s1b : d_s1a;
        const uint4* C2 = layer ? d_s2b : d_s2a;
        const int gl   = tid >> 7;
        const int g    = blockIdx.x * 2 + gl;
        const int lw   = (tid >> 5) & 3;
        const int rel  = lw >> 1;
        const int half = lw & 1;

        const int*   csr = rel ? d_csr_g2 : d_csr_g1;
        const uint4* C   = rel ? C2       : C1;
        const int beg = rel ? d_off_g2[g]  : d_off_g1[g];
        const int cnt = rel ? d_deg_dst2[g]: d_deg_dst1[g];

        float facc[8] = {0,0,0,0,0,0,0,0};
        gather_rows4(C, csr, beg, cnt, half * 32, 64, NC, lane, facc);

        __shared__ float part[8][64];
        if (lane < 8) {
            #pragma unroll
            for (int k = 0; k < 8; k++) part[tid >> 5][il*8 + k] = facc[k];
        }
        __syncthreads();
        if ((tid & 127) < 64) {
            int d = tid & 63;
            float p0 = part[gl*4+0][d], p1 = part[gl*4+1][d];
            float p2 = part[gl*4+2][d], p3 = part[gl*4+3][d];
            float c1s = d_ci1[g], c2s = d_ci2[g];
            float go = 0.5f * (c1s * (p0 + p1) + c2s * (p2 + p3));
            float ih = d_ih[g*64 + d] + W3 * go;
            d_ih[g*64 + d] = ih;
            if (!layer) {
                ((__half*)d_sg1b)[g*64 + d] = __float2half(c1s * go);
                ((__half*)d_sg2b)[g*64 + d] = __float2half(c2s * go);
            } else {
                ((__half*)d_ihh)[g*64 + d] = __float2half(ih);
            }
        }
    } else {
        const uint4* G1 = layer ? d_sg1b : d_sg1a;
        const uint4* G2 = layer ? d_sg2b : d_sg2a;
        const int c   = (blockIdx.x - NGB) * 4 + (tid >> 6);
        const int rel = (tid >> 5) & 1;
        const int lane32 = tid & 31;

        const int*   csr = rel ? d_csr_c2 : d_csr_c1;
        const uint4* G   = rel ? G2       : G1;
        const int beg = rel ? d_off_c2[c]  : d_off_c1[c];
        const int cnt = rel ? d_deg_src2[c]: d_deg_src1[c];

        float facc[8] = {0,0,0,0,0,0,0,0};
        gather_rows4(G, csr, beg, cnt, 0, 32, NG, lane32, facc);

        if (lane32 < 8) {
            float s = rel ? d_cj2[c] : d_cj1[c];
            float v[8];
            #pragma unroll
            for (int k = 0; k < 8; k++) v[k] = s * facc[k];
            float* u = (rel ? d_u2 : d_u1) + c*64 + il*8;
            float4 u0 = ((float4*)u)[0], u1 = ((float4*)u)[1];
            u0.x += W3*v[0]; u0.y += W3*v[1]; u0.z += W3*v[2]; u0.w += W3*v[3];
            u1.x += W3*v[4]; u1.y += W3*v[5]; u1.z += W3*v[6]; u1.w += W3*v[7];
            ((float4*)u)[0] = u0; ((float4*)u)[1] = u1;
            if (!layer) {
                uint4 pk;
                __half2* ph = (__half2*)&pk;
                ph[0] = __floats2half2_rn(s*v[0], s*v[1]);
                ph[1] = __floats2half2_rn(s*v[2], s*v[3]);
                ph[2] = __floats2half2_rn(s*v[4], s*v[5]);
                ph[3] = __floats2half2_rn(s*v[6], s*v[7]);
                (rel ? d_s2b : d_s1b)[c*8 + il] = pk;
            }
        }
    }
}

// ---------------- embed via wmma (padded smem, conflict-free) ---------------
__global__ void emb_kernel(const float* __restrict__ Wm, const float* __restrict__ bb,
                           const float* __restrict__ gam, const float* __restrict__ bet,
                           const float* __restrict__ mu,  const float* __restrict__ var) {
    const int branch = blockIdx.y;
    const float* __restrict__ U = branch ? d_u2 : d_u1;
    __half* __restrict__ UF     = branch ? (__half*)d_ufh2 : (__half*)d_ufh1;

    __shared__ __half sA[64][72];
    __shared__ __half sW[64][72];
    __shared__ float  sC[4][16][68];
    __shared__ float  sScale[64], sShift[64], sBeff[64];

    const int tid = threadIdx.x;
    const int row0 = blockIdx.x * 64;

    for (int t = tid; t < 4096; t += 128)
        sW[t >> 6][t & 63] = __float2half(Wm[t]);
    for (int t = tid; t < 4096; t += 128) {
        int r = t >> 6, k = t & 63;
        int gr = row0 + r;
        sA[r][k] = __float2half(gr < NC ? U[gr*64 + k] : 0.f);
    }
    if (tid < 64) {
        float sc = gam[tid] * rsqrtf(var[tid] + BN_EPS);
        sScale[tid] = sc;
        sShift[tid] = bet[tid] - mu[tid] * sc;
        sBeff[tid]  = bb[tid] + Wm[(64 + branch)*64 + tid];
    }
    __syncthreads();

    const int w = tid >> 5, lane = tid & 31;
    wmma::fragment<wmma::accumulator, 16, 16, 16, float> cf[4];
    #pragma unroll
    for (int n = 0; n < 4; n++) wmma::fill_fragment(cf[n], 0.f);
    #pragma unroll
    for (int k = 0; k < 4; k++) {
        wmma::fragment<wmma::matrix_a, 16, 16, 16, __half, wmma::row_major> af;
        wmma::load_matrix_sync(af, &sA[w*16][k*16], 72);
        #pragma unroll
        for (int n = 0; n < 4; n++) {
            wmma::fragment<wmma::matrix_b, 16, 16, 16, __half, wmma::row_major> bf;
            wmma::load_matrix_sync(bf, &sW[k*16][n*16], 72);
            wmma::mma_sync(cf[n], af, bf, cf[n]);
        }
    }
    #pragma unroll
    for (int n = 0; n < 4; n++)
        wmma::store_matrix_sync(&sC[w][0][n*16], cf[n], 68, wmma::mem_row_major);
    __syncwarp();

    for (int t = lane; t < 1024; t += 32) {
        int r = t >> 6, cc = t & 63;
        int gr = row0 + w*16 + r;
        if (gr < NC) {
            float y = (sC[w][r][cc] + sBeff[cc]) * sScale[cc] + sShift[cc];
            y = y > 0.f ? y : expm1f(y);
            UF[gr*64 + cc] = __float2half(y);
        }
    }
}

// ---------------- decoder: 8 lanes per edge, fp16 rows ----------------------
__global__ void dot_kernel(const int* __restrict__ ps1, const int* __restrict__ pd1,
                           const int* __restrict__ ps2, const int* __restrict__ pd2,
                           float* __restrict__ out) {
    int t = blockIdx.x * blockDim.x + threadIdx.x;
    int e = t >> 3;
    int l = t & 7;
    if (e >= 2*NP) return;
    const uint4* uf; int s, d;
    if (e < NP) { uf = d_ufh1; s = __ldg(&ps1[e]); d = __ldg(&pd1[e]); }
    else { int e2 = e - NP; uf = d_ufh2; s = __ldg(&ps2[e2]); d = __ldg(&pd2[e2]); }
    uint4 A = __ldg(&uf[s*8 + l]);
    uint4 B = __ldg(&d_ihh[d*8 + l]);
    const __half2* ha = (const __half2*)&A;
    const __half2* hb = (const __half2*)&B;
    float v = 0.f;
    #pragma unroll
    for (int k = 0; k < 4; k++) {
        float2 f = __half22float2(__hmul2(ha[k], hb[k]));
        v += f.x + f.y;
    }
    v += __shfl_xor_sync(0xffffffffu, v, 4);
    v += __shfl_xor_sync(0xffffffffu, v, 2);
    v += __shfl_xor_sync(0xffffffffu, v, 1);
    if (l == 0) out[e] = v;
}

// ---------------- host ------------------------------------------------------
extern "C" void kernel_launch(void* const* d_in, const int* in_sizes, int n_in,
                              void* d_out, int out_size) {
    const float* cf1 = (const float*)d_in[0];
    const float* cf2 = (const float*)d_in[1];
    const float* gf  = (const float*)d_in[2];
    const float* Wm  = (const float*)d_in[3];
    const float* bb  = (const float*)d_in[4];
    const float* gam = (const float*)d_in[5];
    const float* bet = (const float*)d_in[6];
    const float* mu  = (const float*)d_in[7];
    const float* var = (const float*)d_in[8];
    const int* es1 = (const int*)d_in[9];
    const int* ed1 = (const int*)d_in[10];
    const int* es2 = (const int*)d_in[11];
    const int* ed2 = (const int*)d_in[12];
    const int* ps1 = (const int*)d_in[13];
    const int* pd1 = (const int*)d_in[14];
    const int* ps2 = (const int*)d_in[15];
    const int* pd2 = (const int*)d_in[16];
    float* out = (float*)d_out;

    zero_kernel<<<(NC + 255)/256, 256>>>();
    hist_kernel<<<(NE/4 + 255)/256, 256>>>((const int4*)es1, (const int4*)ed1,
                                           (const int4*)es2, (const int4*)ed2);
    prep_kernel<<<(NC + 255)/256, 256>>>();
    build_init_kernel<<<SCAT_B + INIT_B, 256>>>((const int4*)es1, (const int4*)ed1,
                                                (const int4*)es2, (const int4*)ed2,
                                                (const float4*)cf1, (const float4*)cf2,
                                                (const float4*)gf);

    layer_kernel<<<NGB + NCB, 256>>>(0);
    layer_kernel<<<NGB + NCB, 256>>>(1);

    emb_kernel<<<dim3((NC + 63)/64, 2), 128>>>(Wm, bb, gam, bet, mu, var);
    dot_kernel<<<(2*NP*8 + 255)/256, 256>>>(ps1, pd1, ps2, pd2, out);
}

// round 13
// speedup vs baseline: 1.3782x; 1.0204x over previous
#include <cuda_runtime.h>
#include <cuda_fp16.h>
#include <mma.h>
#include <math.h>

using namespace nvcuda;

#define NC 50000
#define NG 2000
#define D  64
#define NE 1000000
#define NP 500000
#define W3 (1.0f/3.0f)
#define BN_EPS 1e-5f

#define NGB (NG/2)          // gene blocks (2 genes/block)
#define NCB (NC/4)          // cell blocks (4 cells/block), NC%4==0
#define SCAT_B ((NE/8 + 255)/256)     // scatter blocks (8 edges/thread)
#define INIT_B ((NC*16 + 255)/256)    // scale_init blocks

// ---------------- scratch (static device globals) --------------------------
__device__ int   d_deg_src1[NC], d_deg_src2[NC];
__device__ int   d_deg_dst1[NG], d_deg_dst2[NG];
__device__ int   d_dsh1[NG*8], d_dsh2[NG*8];    // 8-way sharded gene counters
__device__ int   d_goff1[NG*8], d_goff2[NG*8];  // per-shard CSR base offsets
__device__ int   d_off_c1[NC], d_off_c2[NC];
__device__ int   d_off_g1[NG], d_off_g2[NG];
__device__ float d_cj1[NC], d_cj2[NC], d_ci1[NG], d_ci2[NG];
__device__ int   d_ctr[4];
__device__ int   d_rk1[NE], d_rk2[NE];   // packed: cell_rank | ((g_rank<<3|shard)<<16)
__device__ int   d_csr_g1[NE], d_csr_g2[NE];    // cell ids grouped by gene
__device__ int   d_csr_c1[NE], d_csr_c2[NE];    // gene ids grouped by cell
// pre-scaled fp16 tables, 8 x uint4 per row (64 halves); +1 zero dummy row
__device__ uint4 d_s1a[(NC+1)*8], d_s2a[(NC+1)*8];
__device__ uint4 d_s1b[(NC+1)*8], d_s2b[(NC+1)*8];
__device__ uint4 d_sg1a[(NG+1)*8], d_sg2a[(NG+1)*8];
__device__ uint4 d_sg1b[(NG+1)*8], d_sg2b[(NG+1)*8];
__device__ float d_ih[NG*D];
__device__ float d_u1[NC*D],  d_u2[NC*D];
// fp16 decoder tables
__device__ uint4 d_ufh1[NC*8], d_ufh2[NC*8], d_ihh[NG*8];

// ---------------- setup -----------------------------------------------------
__global__ void zero_kernel() {
    int i = blockIdx.x * blockDim.x + threadIdx.x;
    if (i < NC) { d_deg_src1[i]=0; d_deg_src2[i]=0; }
    if (i < NG*8) { d_dsh1[i]=0; d_dsh2[i]=0; }
    if (i < 4)  d_ctr[i] = 0;
    if (i < 8) {
        uint4 z = make_uint4(0,0,0,0);
        d_s1a [NC*8 + i] = z; d_s2a [NC*8 + i] = z;
        d_s1b [NC*8 + i] = z; d_s2b [NC*8 + i] = z;
        d_sg1a[NG*8 + i] = z; d_sg2a[NG*8 + i] = z;
        d_sg1b[NG*8 + i] = z; d_sg2b[NG*8 + i] = z;
    }
}

// single atomic pass: cell counters (low contention) + 8-way sharded gene
// counters (contention/addr ÷8). rank packs: cell | ((g_rank<<3|shard)<<16).
__global__ void hist_kernel(const int4* __restrict__ s1, const int4* __restrict__ t1,
                            const int4* __restrict__ s2, const int4* __restrict__ t2) {
    int i = blockIdx.x * blockDim.x + threadIdx.x;
    if (i >= NE/4) return;
    const int sh = threadIdx.x & 7;
    int4 a = __ldg(&s1[i]), b = __ldg(&t1[i]);
    int4 c = __ldg(&s2[i]), e = __ldg(&t2[i]);
    int4 r;
    r.x = atomicAdd(&d_deg_src1[a.x],1) |
          ((unsigned)((atomicAdd(&d_dsh1[b.x*8+sh],1) << 3) | sh) << 16);
    r.y = atomicAdd(&d_deg_src1[a.y],1) |
          ((unsigned)((atomicAdd(&d_dsh1[b.y*8+sh],1) << 3) | sh) << 16);
    r.z = atomicAdd(&d_deg_src1[a.z],1) |
          ((unsigned)((atomicAdd(&d_dsh1[b.z*8+sh],1) << 3) | sh) << 16);
    r.w = atomicAdd(&d_deg_src1[a.w],1) |
          ((unsigned)((atomicAdd(&d_dsh1[b.w*8+sh],1) << 3) | sh) << 16);
    ((int4*)d_rk1)[i] = r;
    r.x = atomicAdd(&d_deg_src2[c.x],1) |
          ((unsigned)((atomicAdd(&d_dsh2[e.x*8+sh],1) << 3) | sh) << 16);
    r.y = atomicAdd(&d_deg_src2[c.y],1) |
          ((unsigned)((atomicAdd(&d_dsh2[e.y*8+sh],1) << 3) | sh) << 16);
    r.z = atomicAdd(&d_deg_src2[c.z],1) |
          ((unsigned)((atomicAdd(&d_dsh2[e.z*8+sh],1) << 3) | sh) << 16);
    r.w = atomicAdd(&d_deg_src2[c.w],1) |
          ((unsigned)((atomicAdd(&d_dsh2[e.w*8+sh],1) << 3) | sh) << 16);
    ((int4*)d_rk2)[i] = r;
}

__device__ __forceinline__ int warp_alloc(int v, int* ctr, int lane) {
    int x = v;
    #pragma unroll
    for (int d = 1; d < 32; d <<= 1) {
        int y = __shfl_up_sync(0xffffffffu, x, d);
        if (lane >= d) x += y;
    }
    int tot = __shfl_sync(0xffffffffu, x, 31);
    int base = 0;
    if (lane == 31) base = atomicAdd(ctr, tot);
    base = __shfl_sync(0xffffffffu, base, 31);
    return base + x - v;
}

__global__ void prep_kernel() {
    int i = blockIdx.x * blockDim.x + threadIdx.x;
    int lane = threadIdx.x & 31;
    int dg1 = (i < NC) ? d_deg_src1[i] : 0;
    int dg2 = (i < NC) ? d_deg_src2[i] : 0;
    int o1 = warp_alloc(dg1, &d_ctr[0], lane);
    int o2 = warp_alloc(dg2, &d_ctr[1], lane);
    if (i < NC) {
        d_cj1[i] = dg1 ? rsqrtf((float)dg1) : 0.f;
        d_cj2[i] = dg2 ? rsqrtf((float)dg2) : 0.f;
        d_off_c1[i] = o1;
        d_off_c2[i] = o2;
    }
    if (i - lane < NG) {
        int c1[8], c2[8];
        int e1 = 0, e2 = 0;
        if (i < NG) {
            int4 q;
            q = *(const int4*)&d_dsh1[i*8];   c1[0]=q.x; c1[1]=q.y; c1[2]=q.z; c1[3]=q.w;
            q = *(const int4*)&d_dsh1[i*8+4]; c1[4]=q.x; c1[5]=q.y; c1[6]=q.z; c1[7]=q.w;
            q = *(const int4*)&d_dsh2[i*8];   c2[0]=q.x; c2[1]=q.y; c2[2]=q.z; c2[3]=q.w;
            q = *(const int4*)&d_dsh2[i*8+4]; c2[4]=q.x; c2[5]=q.y; c2[6]=q.z; c2[7]=q.w;
            #pragma unroll
            for (int k = 0; k < 8; k++) { e1 += c1[k]; e2 += c2[k]; }
        }
        int p1 = warp_alloc(e1, &d_ctr[2], lane);
        int p2 = warp_alloc(e2, &d_ctr[3], lane);
        if (i < NG) {
            d_ci1[i] = e1 ? rsqrtf((float)e1) : 0.f;
            d_ci2[i] = e2 ? rsqrtf((float)e2) : 0.f;
            d_off_g1[i] = p1;  d_deg_dst1[i] = e1;
            d_off_g2[i] = p2;  d_deg_dst2[i] = e2;
            int run1 = p1, run2 = p2;
            #pragma unroll
            for (int k = 0; k < 8; k++) {
                d_goff1[i*8 + k] = run1; run1 += c1[k];
                d_goff2[i*8 + k] = run2; run2 += c2[k];
            }
        }
    }
}

// merged scatter (latency-bound, 8 edges/thread for MLP) + scale_init (BW-bound)
__global__ void build_init_kernel(const int4* __restrict__ s1, const int4* __restrict__ t1,
                                  const int4* __restrict__ s2, const int4* __restrict__ t2,
                                  const float4* __restrict__ cf1,
                                  const float4* __restrict__ cf2,
                                  const float4* __restrict__ gf) {
    if (blockIdx.x < SCAT_B) {
        int t = blockIdx.x * blockDim.x + threadIdx.x;
        if (t >= NE/8) return;
        #pragma unroll
        for (int half = 0; half < 2; half++) {
            int i = t * 2 + half;
            int4 a = __ldg(&s1[i]), b = __ldg(&t1[i]);
            int4 c = __ldg(&s2[i]), e = __ldg(&t2[i]);
            int4 r1 = __ldg(&((const int4*)d_rk1)[i]);
            int4 r2 = __ldg(&((const int4*)d_rk2)[i]);
            int sa[4] = {a.x,a.y,a.z,a.w}, ta[4] = {b.x,b.y,b.z,b.w};
            int sc[4] = {c.x,c.y,c.z,c.w}, tc[4] = {e.x,e.y,e.z,e.w};
            int k1[4] = {r1.x,r1.y,r1.z,r1.w}, k2[4] = {r2.x,r2.y,r2.z,r2.w};
            #pragma unroll
            for (int k = 0; k < 4; k++) {
                d_csr_c1[__ldg(&d_off_c1[sa[k]]) + (k1[k] & 0xffff)] = ta[k];
                unsigned gf1 = ((unsigned)k1[k]) >> 16;
                d_csr_g1[__ldg(&d_goff1[ta[k]*8 + (gf1 & 7)]) + (gf1 >> 3)] = sa[k];
                d_csr_c2[__ldg(&d_off_c2[sc[k]]) + (k2[k] & 0xffff)] = tc[k];
                unsigned gf2 = ((unsigned)k2[k]) >> 16;
                d_csr_g2[__ldg(&d_goff2[tc[k]*8 + (gf2 & 7)]) + (gf2 >> 3)] = sc[k];
            }
        }
    } else {
        int i = (blockIdx.x - SCAT_B) * blockDim.x + threadIdx.x;
        if (i < NC*16) {
            int row = i >> 4;
            float4 x1 = __ldg(&cf1[i]), x2 = __ldg(&cf2[i]);
            float w1 = __ldg(&d_cj1[row]), w2 = __ldg(&d_cj2[row]);
            ((float4*)d_u1)[i] = make_float4(W3*x1.x, W3*x1.y, W3*x1.z, W3*x1.w);
            ((float4*)d_u2)[i] = make_float4(W3*x2.x, W3*x2.y, W3*x2.z, W3*x2.w);
            ((__half2*)d_s1a)[2*i]   = __floats2half2_rn(w1*x1.x, w1*x1.y);
            ((__half2*)d_s1a)[2*i+1] = __floats2half2_rn(w1*x1.z, w1*x1.w);
            ((__half2*)d_s2a)[2*i]   = __floats2half2_rn(w2*x2.x, w2*x2.y);
            ((__half2*)d_s2a)[2*i+1] = __floats2half2_rn(w2*x2.z, w2*x2.w);
        }
        if (i < NG*16) {
            int row = i >> 4;
            float4 g = __ldg(&gf[i]);
            float w1 = __ldg(&d_ci1[row]), w2 = __ldg(&d_ci2[row]);
            ((float4*)d_ih)[i] = make_float4(W3*g.x, W3*g.y, W3*g.z, W3*g.w);
            ((__half2*)d_sg1a)[2*i]   = __floats2half2_rn(w1*g.x, w1*g.y);
            ((__half2*)d_sg1a)[2*i+1] = __floats2half2_rn(w1*g.z, w1*g.w);
            ((__half2*)d_sg2a)[2*i]   = __floats2half2_rn(w2*g.x, w2*g.y);
            ((__half2*)d_sg2a)[2*i+1] = __floats2half2_rn(w2*g.z, w2*g.w);
        }
    }
}

// ---------------- gather: branch-free batches + index prefetch --------------
__device__ __forceinline__ void gather_rows4(const uint4* __restrict__ C,
                                             const int* __restrict__ csr,
                                             int beg, int cnt, int start, int step,
                                             int dummy, int lane, float* facc) {
    const int grp = lane >> 3, il = lane & 7;
    const __half2 z = __float2half2_rn(0.f);
    int base = start;
    int p0 = base + lane;
    int idx = (p0 < cnt) ? __ldg(&csr[beg + p0]) : dummy;
    for (; base < cnt; base += step) {
        int nb = base + step;
        int np = nb + lane;
        int nidx = (nb < cnt && np < cnt) ? __ldg(&csr[beg + np]) : dummy;

        __half2 a[8];
        #pragma unroll
        for (int k = 0; k < 8; k++) a[k] = z;
        #pragma unroll
        for (int j = 0; j < 32; j += 4) {
            int bi = __shfl_sync(0xffffffffu, idx, j + grp);
            uint4 r = __ldg(&C[bi*8 + il]);
            const __half2* h = (const __half2*)&r;
            const int q = j & 4;
            a[q+0] = __hadd2(a[q+0], h[0]);
            a[q+1] = __hadd2(a[q+1], h[1]);
            a[q+2] = __hadd2(a[q+2], h[2]);
            a[q+3] = __hadd2(a[q+3], h[3]);
        }
        #pragma unroll
        for (int k = 0; k < 8; k++) {
            float2 f = __half22float2(a[k]);
            facc[2*(k & 3)]     += f.x;
            facc[2*(k & 3) + 1] += f.y;
        }
        idx = nidx;
    }
    #pragma unroll
    for (int k = 0; k < 8; k++) {
        facc[k] += __shfl_xor_sync(0xffffffffu, facc[k], 8);
        facc[k] += __shfl_xor_sync(0xffffffffu, facc[k], 16);
    }
}

// ---------------- fused per-layer SpMM --------------------------------------
// launch_bounds(256,5): cap regs ~51 -> 5 blocks/SM = 10 warps/SMSP (was 8)
__global__ void __launch_bounds__(256, 5) layer_kernel(int layer) {
    const int tid  = threadIdx.x;
    const int lane = tid & 31;
    const int il   = lane & 7;

    if (blockIdx.x < NGB) {
        const uint4* C1 = layer ? d_s1b : d_s1a;
        const uint4* C2 = layer ? d_s2b : d_s2a;
        const int gl   = tid >> 7;
        const int g    = blockIdx.x * 2 + gl;
        const int lw   = (tid >> 5) & 3;
        const int rel  = lw >> 1;
        const int half = lw & 1;

        const int*   csr = rel ? d_csr_g2 : d_csr_g1;
        const uint4* C   = rel ? C2       : C1;
        const int beg = rel ? d_off_g2[g]  : d_off_g1[g];
        const int cnt = rel ? d_deg_dst2[g]: d_deg_dst1[g];

        float facc[8] = {0,0,0,0,0,0,0,0};
        gather_rows4(C, csr, beg, cnt, half * 32, 64, NC, lane, facc);

        __shared__ float part[8][64];
        if (lane < 8) {
            #pragma unroll
            for (int k = 0; k < 8; k++) part[tid >> 5][il*8 + k] = facc[k];
        }
        __syncthreads();
        if ((tid & 127) < 64) {
            int d = tid & 63;
            float p0 = part[gl*4+0][d], p1 = part[gl*4+1][d];
            float p2 = part[gl*4+2][d], p3 = part[gl*4+3][d];
            float c1s = d_ci1[g], c2s = d_ci2[g];
            float go = 0.5f * (c1s * (p0 + p1) + c2s * (p2 + p3));
            float ih = d_ih[g*64 + d] + W3 * go;
            d_ih[g*64 + d] = ih;
            if (!layer) {
                ((__half*)d_sg1b)[g*64 + d] = __float2half(c1s * go);
                ((__half*)d_sg2b)[g*64 + d] = __float2half(c2s * go);
            } else {
                ((__half*)d_ihh)[g*64 + d] = __float2half(ih);
            }
        }
    } else {
        const uint4* G1 = layer ? d_sg1b : d_sg1a;
        const uint4* G2 = layer ? d_sg2b : d_sg2a;
        const int c   = (blockIdx.x - NGB) * 4 + (tid >> 6);
        const int rel = (tid >> 5) & 1;
        const int lane32 = tid & 31;

        const int*   csr = rel ? d_csr_c2 : d_csr_c1;
        const uint4* G   = rel ? G2       : G1;
        const int beg = rel ? d_off_c2[c]  : d_off_c1[c];
        const int cnt = rel ? d_deg_src2[c]: d_deg_src1[c];

        float facc[8] = {0,0,0,0,0,0,0,0};
        gather_rows4(G, csr, beg, cnt, 0, 32, NG, lane32, facc);

        if (lane32 < 8) {
            float s = rel ? d_cj2[c] : d_cj1[c];
            float v[8];
            #pragma unroll
            for (int k = 0; k < 8; k++) v[k] = s * facc[k];
            float* u = (rel ? d_u2 : d_u1) + c*64 + il*8;
            float4 u0 = ((float4*)u)[0], u1 = ((float4*)u)[1];
            u0.x += W3*v[0]; u0.y += W3*v[1]; u0.z += W3*v[2]; u0.w += W3*v[3];
            u1.x += W3*v[4]; u1.y += W3*v[5]; u1.z += W3*v[6]; u1.w += W3*v[7];
            ((float4*)u)[0] = u0; ((float4*)u)[1] = u1;
            if (!layer) {
                uint4 pk;
                __half2* ph = (__half2*)&pk;
                ph[0] = __floats2half2_rn(s*v[0], s*v[1]);
                ph[1] = __floats2half2_rn(s*v[2], s*v[3]);
                ph[2] = __floats2half2_rn(s*v[4], s*v[5]);
                ph[3] = __floats2half2_rn(s*v[6], s*v[7]);
                (rel ? d_s2b : d_s1b)[c*8 + il] = pk;
            }
        }
    }
}

// ---------------- embed via wmma (padded smem, conflict-free) ---------------
__global__ void emb_kernel(const float* __restrict__ Wm, const float* __restrict__ bb,
                           const float* __restrict__ gam, const float* __restrict__ bet,
                           const float* __restrict__ mu,  const float* __restrict__ var) {
    const int branch = blockIdx.y;
    const float* __restrict__ U = branch ? d_u2 : d_u1;
    __half* __restrict__ UF     = branch ? (__half*)d_ufh2 : (__half*)d_ufh1;

    __shared__ __half sA[64][72];
    __shared__ __half sW[64][72];
    __shared__ float  sC[4][16][68];
    __shared__ float  sScale[64], sShift[64], sBeff[64];

    const int tid = threadIdx.x;
    const int row0 = blockIdx.x * 64;

    for (int t = tid; t < 4096; t += 128)
        sW[t >> 6][t & 63] = __float2half(Wm[t]);
    for (int t = tid; t < 4096; t += 128) {
        int r = t >> 6, k = t & 63;
        int gr = row0 + r;
        sA[r][k] = __float2half(gr < NC ? U[gr*64 + k] : 0.f);
    }
    if (tid < 64) {
        float sc = gam[tid] * rsqrtf(var[tid] + BN_EPS);
        sScale[tid] = sc;
        sShift[tid] = bet[tid] - mu[tid] * sc;
        sBeff[tid]  = bb[tid] + Wm[(64 + branch)*64 + tid];
    }
    __syncthreads();

    const int w = tid >> 5, lane = tid & 31;
    wmma::fragment<wmma::accumulator, 16, 16, 16, float> cf[4];
    #pragma unroll
    for (int n = 0; n < 4; n++) wmma::fill_fragment(cf[n], 0.f);
    #pragma unroll
    for (int k = 0; k < 4; k++) {
        wmma::fragment<wmma::matrix_a, 16, 16, 16, __half, wmma::row_major> af;
        wmma::load_matrix_sync(af, &sA[w*16][k*16], 72);
        #pragma unroll
        for (int n = 0; n < 4; n++) {
            wmma::fragment<wmma::matrix_b, 16, 16, 16, __half, wmma::row_major> bf;
            wmma::load_matrix_sync(bf, &sW[k*16][n*16], 72);
            wmma::mma_sync(cf[n], af, bf, cf[n]);
        }
    }
    #pragma unroll
    for (int n = 0; n < 4; n++)
        wmma::store_matrix_sync(&sC[w][0][n*16], cf[n], 68, wmma::mem_row_major);
    __syncwarp();

    for (int t = lane; t < 1024; t += 32) {
        int r = t >> 6, cc = t & 63;
        int gr = row0 + w*16 + r;
        if (gr < NC) {
            float y = (sC[w][r][cc] + sBeff[cc]) * sScale[cc] + sShift[cc];
            y = y > 0.f ? y : expm1f(y);
            UF[gr*64 + cc] = __float2half(y);
        }
    }
}

// ---------------- decoder: 8 lanes per edge, fp16 rows ----------------------
__global__ void dot_kernel(const int* __restrict__ ps1, const int* __restrict__ pd1,
                           const int* __restrict__ ps2, const int* __restrict__ pd2,
                           float* __restrict__ out) {
    int t = blockIdx.x * blockDim.x + threadIdx.x;
    int e = t >> 3;
    int l = t & 7;
    if (e >= 2*NP) return;
    const uint4* uf; int s, d;
    if (e < NP) { uf = d_ufh1; s = __ldg(&ps1[e]); d = __ldg(&pd1[e]); }
    else { int e2 = e - NP; uf = d_ufh2; s = __ldg(&ps2[e2]); d = __ldg(&pd2[e2]); }
    uint4 A = __ldg(&uf[s*8 + l]);
    uint4 B = __ldg(&d_ihh[d*8 + l]);
    const __half2* ha = (const __half2*)&A;
    const __half2* hb = (const __half2*)&B;
    float v = 0.f;
    #pragma unroll
    for (int k = 0; k < 4; k++) {
        float2 f = __half22float2(__hmul2(ha[k], hb[k]));
        v += f.x + f.y;
    }
    v += __shfl_xor_sync(0xffffffffu, v, 4);
    v += __shfl_xor_sync(0xffffffffu, v, 2);
    v += __shfl_xor_sync(0xffffffffu, v, 1);
    if (l == 0) out[e] = v;
}

// ---------------- host ------------------------------------------------------
extern "C" void kernel_launch(void* const* d_in, const int* in_sizes, int n_in,
                              void* d_out, int out_size) {
    const float* cf1 = (const float*)d_in[0];
    const float* cf2 = (const float*)d_in[1];
    const float* gf  = (const float*)d_in[2];
    const float* Wm  = (const float*)d_in[3];
    const float* bb  = (const float*)d_in[4];
    const float* gam = (const float*)d_in[5];
    const float* bet = (const float*)d_in[6];
    const float* mu  = (const float*)d_in[7];
    const float* var = (const float*)d_in[8];
    const int* es1 = (const int*)d_in[9];
    const int* ed1 = (const int*)d_in[10];
    const int* es2 = (const int*)d_in[11];
    const int* ed2 = (const int*)d_in[12];
    const int* ps1 = (const int*)d_in[13];
    const int* pd1 = (const int*)d_in[14];
    const int* ps2 = (const int*)d_in[15];
    const int* pd2 = (const int*)d_in[16];
    float* out = (float*)d_out;

    zero_kernel<<<(NC + 255)/256, 256>>>();
    hist_kernel<<<(NE/4 + 255)/256, 256>>>((const int4*)es1, (const int4*)ed1,
                                           (const int4*)es2, (const int4*)ed2);
    prep_kernel<<<(NC + 255)/256, 256>>>();
    build_init_kernel<<<SCAT_B + INIT_B, 256>>>((const int4*)es1, (const int4*)ed1,
                                                (const int4*)es2, (const int4*)ed2,
                                                (const float4*)cf1, (const float4*)cf2,
                                                (const float4*)gf);

    layer_kernel<<<NGB + NCB, 256>>>(0);
    layer_kernel<<<NGB + NCB, 256>>>(1);

    emb_kernel<<<dim3((NC + 63)/64, 2), 128>>>(Wm, bb, gam, bet, mu, var);
    dot_kernel<<<(2*NP*8 + 255)/256, 256>>>(ps1, pd1, ps2, pd2, out);
}

// round 14
// speedup vs baseline: 1.3981x; 1.0144x over previous
#include <cuda_runtime.h>
#include <cuda_fp16.h>
#include <mma.h>
#include <math.h>

using namespace nvcuda;

#define NC 50000
#define NG 2000
#define D  64
#define NE 1000000
#define NP 500000
#define W3 (1.0f/3.0f)
#define BN_EPS 1e-5f

#define NGB (NG/2)          // gene blocks (2 genes/block)
#define NCB (NC/4)          // cell blocks (4 cells/block), NC%4==0
#define SCAT_B ((NE/4 + 255)/256)     // scatter blocks (4 edges/thread)
#define INIT_B ((NC*16 + 255)/256)    // scale_init blocks

// ---------------- scratch (static device globals) --------------------------
__device__ int   d_deg_src1[NC], d_deg_src2[NC];
__device__ int   d_deg_dst1[NG], d_deg_dst2[NG];
__device__ int   d_dsh1[NG*8], d_dsh2[NG*8];    // 8-way sharded gene counters
__device__ int   d_goff1[NG*8], d_goff2[NG*8];  // per-shard CSR base offsets
__device__ int   d_off_c1[NC], d_off_c2[NC];
__device__ int   d_off_g1[NG], d_off_g2[NG];
__device__ float d_cj1[NC], d_cj2[NC], d_ci1[NG], d_ci2[NG];
__device__ int   d_ctr[4];
__device__ int   d_rk1[NE], d_rk2[NE];   // packed: cell_rank | ((g_rank<<3|shard)<<16)
__device__ int   d_csr_g1[NE], d_csr_g2[NE];    // cell ids grouped by gene
__device__ int   d_csr_c1[NE], d_csr_c2[NE];    // gene ids grouped by cell
// pre-scaled fp16 tables, 8 x uint4 per row (64 halves); +1 zero dummy row
__device__ uint4 d_s1a[(NC+1)*8], d_s2a[(NC+1)*8];
__device__ uint4 d_s1b[(NC+1)*8], d_s2b[(NC+1)*8];
__device__ uint4 d_sg1a[(NG+1)*8], d_sg2a[(NG+1)*8];
__device__ uint4 d_sg1b[(NG+1)*8], d_sg2b[(NG+1)*8];
__device__ float d_ih[NG*D];
__device__ float d_u1[NC*D],  d_u2[NC*D];
// fp16 decoder tables
__device__ uint4 d_ufh1[NC*8], d_ufh2[NC*8], d_ihh[NG*8];

// ---------------- setup -----------------------------------------------------
__global__ void zero_kernel() {
    int i = blockIdx.x * blockDim.x + threadIdx.x;
    if (i < NC) { d_deg_src1[i]=0; d_deg_src2[i]=0; }
    if (i < NG*8) { d_dsh1[i]=0; d_dsh2[i]=0; }
    if (i < 4)  d_ctr[i] = 0;
    if (i < 8) {
        uint4 z = make_uint4(0,0,0,0);
        d_s1a [NC*8 + i] = z; d_s2a [NC*8 + i] = z;
        d_s1b [NC*8 + i] = z; d_s2b [NC*8 + i] = z;
        d_sg1a[NG*8 + i] = z; d_sg2a[NG*8 + i] = z;
        d_sg1b[NG*8 + i] = z; d_sg2b[NG*8 + i] = z;
    }
}

// single atomic pass: cell counters (low contention) + 8-way sharded gene
// counters (contention/addr ÷8). rank packs: cell | ((g_rank<<3|shard)<<16).
__global__ void hist_kernel(const int4* __restrict__ s1, const int4* __restrict__ t1,
                            const int4* __restrict__ s2, const int4* __restrict__ t2) {
    int i = blockIdx.x * blockDim.x + threadIdx.x;
    if (i >= NE/4) return;
    const int sh = threadIdx.x & 7;
    int4 a = __ldg(&s1[i]), b = __ldg(&t1[i]);
    int4 c = __ldg(&s2[i]), e = __ldg(&t2[i]);
    int4 r;
    r.x = atomicAdd(&d_deg_src1[a.x],1) |
          ((unsigned)((atomicAdd(&d_dsh1[b.x*8+sh],1) << 3) | sh) << 16);
    r.y = atomicAdd(&d_deg_src1[a.y],1) |
          ((unsigned)((atomicAdd(&d_dsh1[b.y*8+sh],1) << 3) | sh) << 16);
    r.z = atomicAdd(&d_deg_src1[a.z],1) |
          ((unsigned)((atomicAdd(&d_dsh1[b.z*8+sh],1) << 3) | sh) << 16);
    r.w = atomicAdd(&d_deg_src1[a.w],1) |
          ((unsigned)((atomicAdd(&d_dsh1[b.w*8+sh],1) << 3) | sh) << 16);
    ((int4*)d_rk1)[i] = r;
    r.x = atomicAdd(&d_deg_src2[c.x],1) |
          ((unsigned)((atomicAdd(&d_dsh2[e.x*8+sh],1) << 3) | sh) << 16);
    r.y = atomicAdd(&d_deg_src2[c.y],1) |
          ((unsigned)((atomicAdd(&d_dsh2[e.y*8+sh],1) << 3) | sh) << 16);
    r.z = atomicAdd(&d_deg_src2[c.z],1) |
          ((unsigned)((atomicAdd(&d_dsh2[e.z*8+sh],1) << 3) | sh) << 16);
    r.w = atomicAdd(&d_deg_src2[c.w],1) |
          ((unsigned)((atomicAdd(&d_dsh2[e.w*8+sh],1) << 3) | sh) << 16);
    ((int4*)d_rk2)[i] = r;
}

__device__ __forceinline__ int warp_alloc(int v, int* ctr, int lane) {
    int x = v;
    #pragma unroll
    for (int d = 1; d < 32; d <<= 1) {
        int y = __shfl_up_sync(0xffffffffu, x, d);
        if (lane >= d) x += y;
    }
    int tot = __shfl_sync(0xffffffffu, x, 31);
    int base = 0;
    if (lane == 31) base = atomicAdd(ctr, tot);
    base = __shfl_sync(0xffffffffu, base, 31);
    return base + x - v;
}

__global__ void prep_kernel() {
    int i = blockIdx.x * blockDim.x + threadIdx.x;
    int lane = threadIdx.x & 31;
    int dg1 = (i < NC) ? d_deg_src1[i] : 0;
    int dg2 = (i < NC) ? d_deg_src2[i] : 0;
    int o1 = warp_alloc(dg1, &d_ctr[0], lane);
    int o2 = warp_alloc(dg2, &d_ctr[1], lane);
    if (i < NC) {
        d_cj1[i] = dg1 ? rsqrtf((float)dg1) : 0.f;
        d_cj2[i] = dg2 ? rsqrtf((float)dg2) : 0.f;
        d_off_c1[i] = o1;
        d_off_c2[i] = o2;
    }
    if (i - lane < NG) {
        int c1[8], c2[8];
        int e1 = 0, e2 = 0;
        if (i < NG) {
            int4 q;
            q = *(const int4*)&d_dsh1[i*8];   c1[0]=q.x; c1[1]=q.y; c1[2]=q.z; c1[3]=q.w;
            q = *(const int4*)&d_dsh1[i*8+4]; c1[4]=q.x; c1[5]=q.y; c1[6]=q.z; c1[7]=q.w;
            q = *(const int4*)&d_dsh2[i*8];   c2[0]=q.x; c2[1]=q.y; c2[2]=q.z; c2[3]=q.w;
            q = *(const int4*)&d_dsh2[i*8+4]; c2[4]=q.x; c2[5]=q.y; c2[6]=q.z; c2[7]=q.w;
            #pragma unroll
            for (int k = 0; k < 8; k++) { e1 += c1[k]; e2 += c2[k]; }
        }
        int p1 = warp_alloc(e1, &d_ctr[2], lane);
        int p2 = warp_alloc(e2, &d_ctr[3], lane);
        if (i < NG) {
            d_ci1[i] = e1 ? rsqrtf((float)e1) : 0.f;
            d_ci2[i] = e2 ? rsqrtf((float)e2) : 0.f;
            d_off_g1[i] = p1;  d_deg_dst1[i] = e1;
            d_off_g2[i] = p2;  d_deg_dst2[i] = e2;
            int run1 = p1, run2 = p2;
            #pragma unroll
            for (int k = 0; k < 8; k++) {
                d_goff1[i*8 + k] = run1; run1 += c1[k];
                d_goff2[i*8 + k] = run2; run2 += c2[k];
            }
        }
    }
}

// merged scatter (latency-bound, 4 edges/thread — 8/thread regressed: regs 64,
// occ 44% vs 57%; occupancy beats per-thread MLP here) + scale_init (BW-bound)
__global__ void build_init_kernel(const int4* __restrict__ s1, const int4* __restrict__ t1,
                                  const int4* __restrict__ s2, const int4* __restrict__ t2,
                                  const float4* __restrict__ cf1,
                                  const float4* __restrict__ cf2,
                                  const float4* __restrict__ gf) {
    if (blockIdx.x < SCAT_B) {
        int i = blockIdx.x * blockDim.x + threadIdx.x;
        if (i >= NE/4) return;
        int4 a = __ldg(&s1[i]), b = __ldg(&t1[i]);
        int4 c = __ldg(&s2[i]), e = __ldg(&t2[i]);
        int4 r1 = __ldg(&((const int4*)d_rk1)[i]);
        int4 r2 = __ldg(&((const int4*)d_rk2)[i]);
        int sa[4] = {a.x,a.y,a.z,a.w}, ta[4] = {b.x,b.y,b.z,b.w};
        int sc[4] = {c.x,c.y,c.z,c.w}, tc[4] = {e.x,e.y,e.z,e.w};
        int k1[4] = {r1.x,r1.y,r1.z,r1.w}, k2[4] = {r2.x,r2.y,r2.z,r2.w};
        #pragma unroll
        for (int k = 0; k < 4; k++) {
            d_csr_c1[__ldg(&d_off_c1[sa[k]]) + (k1[k] & 0xffff)] = ta[k];
            unsigned gf1 = ((unsigned)k1[k]) >> 16;
            d_csr_g1[__ldg(&d_goff1[ta[k]*8 + (gf1 & 7)]) + (gf1 >> 3)] = sa[k];
            d_csr_c2[__ldg(&d_off_c2[sc[k]]) + (k2[k] & 0xffff)] = tc[k];
            unsigned gf2 = ((unsigned)k2[k]) >> 16;
            d_csr_g2[__ldg(&d_goff2[tc[k]*8 + (gf2 & 7)]) + (gf2 >> 3)] = sc[k];
        }
    } else {
        int i = (blockIdx.x - SCAT_B) * blockDim.x + threadIdx.x;
        if (i < NC*16) {
            int row = i >> 4;
            float4 x1 = __ldg(&cf1[i]), x2 = __ldg(&cf2[i]);
            float w1 = __ldg(&d_cj1[row]), w2 = __ldg(&d_cj2[row]);
            ((float4*)d_u1)[i] = make_float4(W3*x1.x, W3*x1.y, W3*x1.z, W3*x1.w);
            ((float4*)d_u2)[i] = make_float4(W3*x2.x, W3*x2.y, W3*x2.z, W3*x2.w);
            ((__half2*)d_s1a)[2*i]   = __floats2half2_rn(w1*x1.x, w1*x1.y);
            ((__half2*)d_s1a)[2*i+1] = __floats2half2_rn(w1*x1.z, w1*x1.w);
            ((__half2*)d_s2a)[2*i]   = __floats2half2_rn(w2*x2.x, w2*x2.y);
            ((__half2*)d_s2a)[2*i+1] = __floats2half2_rn(w2*x2.z, w2*x2.w);
        }
        if (i < NG*16) {
            int row = i >> 4;
            float4 g = __ldg(&gf[i]);
            float w1 = __ldg(&d_ci1[row]), w2 = __ldg(&d_ci2[row]);
            ((float4*)d_ih)[i] = make_float4(W3*g.x, W3*g.y, W3*g.z, W3*g.w);
            ((__half2*)d_sg1a)[2*i]   = __floats2half2_rn(w1*g.x, w1*g.y);
            ((__half2*)d_sg1a)[2*i+1] = __floats2half2_rn(w1*g.z, w1*g.w);
            ((__half2*)d_sg2a)[2*i]   = __floats2half2_rn(w2*g.x, w2*g.y);
            ((__half2*)d_sg2a)[2*i+1] = __floats2half2_rn(w2*g.z, w2*g.w);
        }
    }
}

// ---------------- gather: branch-free batches + index prefetch --------------
__device__ __forceinline__ void gather_rows4(const uint4* __restrict__ C,
                                             const int* __restrict__ csr,
                                             int beg, int cnt, int start, int step,
                                             int dummy, int lane, float* facc) {
    const int grp = lane >> 3, il = lane & 7;
    const __half2 z = __float2half2_rn(0.f);
    int base = start;
    int p0 = base + lane;
    int idx = (p0 < cnt) ? __ldg(&csr[beg + p0]) : dummy;
    for (; base < cnt; base += step) {
        int nb = base + step;
        int np = nb + lane;
        int nidx = (nb < cnt && np < cnt) ? __ldg(&csr[beg + np]) : dummy;

        __half2 a[8];
        #pragma unroll
        for (int k = 0; k < 8; k++) a[k] = z;
        #pragma unroll
        for (int j = 0; j < 32; j += 4) {
            int bi = __shfl_sync(0xffffffffu, idx, j + grp);
            uint4 r = __ldg(&C[bi*8 + il]);
            const __half2* h = (const __half2*)&r;
            const int q = j & 4;
            a[q+0] = __hadd2(a[q+0], h[0]);
            a[q+1] = __hadd2(a[q+1], h[1]);
            a[q+2] = __hadd2(a[q+2], h[2]);
            a[q+3] = __hadd2(a[q+3], h[3]);
        }
        #pragma unroll
        for (int k = 0; k < 8; k++) {
            float2 f = __half22float2(a[k]);
            facc[2*(k & 3)]     += f.x;
            facc[2*(k & 3) + 1] += f.y;
        }
        idx = nidx;
    }
    #pragma unroll
    for (int k = 0; k < 8; k++) {
        facc[k] += __shfl_xor_sync(0xffffffffu, facc[k], 8);
        facc[k] += __shfl_xor_sync(0xffffffffu, facc[k], 16);
    }
}

// ---------------- fused per-layer SpMM --------------------------------------
// launch_bounds(256,5): cap regs ~51 -> 5 blocks/SM = 10 warps/SMSP
__global__ void __launch_bounds__(256, 5) layer_kernel(int layer) {
    const int tid  = threadIdx.x;
    const int lane = tid & 31;
    const int il   = lane & 7;

    if (blockIdx.x < NGB) {
        const uint4* C1 = layer ? d_s1b : d_s1a;
        const uint4* C2 = layer ? d_s2b : d_s2a;
        const int gl   = tid >> 7;
        const int g    = blockIdx.x * 2 + gl;
        const int lw   = (tid >> 5) & 3;
        const int rel  = lw >> 1;
        const int half = lw & 1;

        const int*   csr = rel ? d_csr_g2 : d_csr_g1;
        const uint4* C   = rel ? C2       : C1;
        const int beg = rel ? d_off_g2[g]  : d_off_g1[g];
        const int cnt = rel ? d_deg_dst2[g]: d_deg_dst1[g];

        float facc[8] = {0,0,0,0,0,0,0,0};
        gather_rows4(C, csr, beg, cnt, half * 32, 64, NC, lane, facc);

        __shared__ float part[8][64];
        if (lane < 8) {
            #pragma unroll
            for (int k = 0; k < 8; k++) part[tid >> 5][il*8 + k] = facc[k];
        }
        __syncthreads();
        if ((tid & 127) < 64) {
            int d = tid & 63;
            float p0 = part[gl*4+0][d], p1 = part[gl*4+1][d];
            float p2 = part[gl*4+2][d], p3 = part[gl*4+3][d];
            float c1s = d_ci1[g], c2s = d_ci2[g];
            float go = 0.5f * (c1s * (p0 + p1) + c2s * (p2 + p3));
            float ih = d_ih[g*64 + d] + W3 * go;
            d_ih[g*64 + d] = ih;
            if (!layer) {
                ((__half*)d_sg1b)[g*64 + d] = __float2half(c1s * go);
                ((__half*)d_sg2b)[g*64 + d] = __float2half(c2s * go);
            } else {
                ((__half*)d_ihh)[g*64 + d] = __float2half(ih);
            }
        }
    } else {
        const uint4* G1 = layer ? d_sg1b : d_sg1a;
        const uint4* G2 = layer ? d_sg2b : d_sg2a;
        const int c   = (blockIdx.x - NGB) * 4 + (tid >> 6);
        const int rel = (tid >> 5) & 1;
        const int lane32 = tid & 31;

        const int*   csr = rel ? d_csr_c2 : d_csr_c1;
        const uint4* G   = rel ? G2       : G1;
        const int beg = rel ? d_off_c2[c]  : d_off_c1[c];
        const int cnt = rel ? d_deg_src2[c]: d_deg_src1[c];

        float facc[8] = {0,0,0,0,0,0,0,0};
        gather_rows4(G, csr, beg, cnt, 0, 32, NG, lane32, facc);

        if (lane32 < 8) {
            float s = rel ? d_cj2[c] : d_cj1[c];
            float v[8];
            #pragma unroll
            for (int k = 0; k < 8; k++) v[k] = s * facc[k];
            float* u = (rel ? d_u2 : d_u1) + c*64 + il*8;
            float4 u0 = ((float4*)u)[0], u1 = ((float4*)u)[1];
            u0.x += W3*v[0]; u0.y += W3*v[1]; u0.z += W3*v[2]; u0.w += W3*v[3];
            u1.x += W3*v[4]; u1.y += W3*v[5]; u1.z += W3*v[6]; u1.w += W3*v[7];
            ((float4*)u)[0] = u0; ((float4*)u)[1] = u1;
            if (!layer) {
                uint4 pk;
                __half2* ph = (__half2*)&pk;
                ph[0] = __floats2half2_rn(s*v[0], s*v[1]);
                ph[1] = __floats2half2_rn(s*v[2], s*v[3]);
                ph[2] = __floats2half2_rn(s*v[4], s*v[5]);
                ph[3] = __floats2half2_rn(s*v[6], s*v[7]);
                (rel ? d_s2b : d_s1b)[c*8 + il] = pk;
            }
        }
    }
}

// ---------------- embed via wmma (padded smem, conflict-free) ---------------
__global__ void emb_kernel(const float* __restrict__ Wm, const float* __restrict__ bb,
                           const float* __restrict__ gam, const float* __restrict__ bet,
                           const float* __restrict__ mu,  const float* __restrict__ var) {
    const int branch = blockIdx.y;
    const float* __restrict__ U = branch ? d_u2 : d_u1;
    __half* __restrict__ UF     = branch ? (__half*)d_ufh2 : (__half*)d_ufh1;

    __shared__ __half sA[64][72];
    __shared__ __half sW[64][72];
    __shared__ float  sC[4][16][68];
    __shared__ float  sScale[64], sShift[64], sBeff[64];

    const int tid = threadIdx.x;
    const int row0 = blockIdx.x * 64;

    for (int t = tid; t < 4096; t += 128)
        sW[t >> 6][t & 63] = __float2half(Wm[t]);
    for (int t = tid; t < 4096; t += 128) {
        int r = t >> 6, k = t & 63;
        int gr = row0 + r;
        sA[r][k] = __float2half(gr < NC ? U[gr*64 + k] : 0.f);
    }
    if (tid < 64) {
        float sc = gam[tid] * rsqrtf(var[tid] + BN_EPS);
        sScale[tid] = sc;
        sShift[tid] = bet[tid] - mu[tid] * sc;
        sBeff[tid]  = bb[tid] + Wm[(64 + branch)*64 + tid];
    }
    __syncthreads();

    const int w = tid >> 5, lane = tid & 31;
    wmma::fragment<wmma::accumulator, 16, 16, 16, float> cf[4];
    #pragma unroll
    for (int n = 0; n < 4; n++) wmma::fill_fragment(cf[n], 0.f);
    #pragma unroll
    for (int k = 0; k < 4; k++) {
        wmma::fragment<wmma::matrix_a, 16, 16, 16, __half, wmma::row_major> af;
        wmma::load_matrix_sync(af, &sA[w*16][k*16], 72);
        #pragma unroll
        for (int n = 0; n < 4; n++) {
            wmma::fragment<wmma::matrix_b, 16, 16, 16, __half, wmma::row_major> bf;
            wmma::load_matrix_sync(bf, &sW[k*16][n*16], 72);
            wmma::mma_sync(cf[n], af, bf, cf[n]);
        }
    }
    #pragma unroll
    for (int n = 0; n < 4; n++)
        wmma::store_matrix_sync(&sC[w][0][n*16], cf[n], 68, wmma::mem_row_major);
    __syncwarp();

    for (int t = lane; t < 1024; t += 32) {
        int r = t >> 6, cc = t & 63;
        int gr = row0 + w*16 + r;
        if (gr < NC) {
            float y = (sC[w][r][cc] + sBeff[cc]) * sScale[cc] + sShift[cc];
            y = y > 0.f ? y : expm1f(y);
            UF[gr*64 + cc] = __float2half(y);
        }
    }
}

// ---------------- decoder: 8 lanes per edge, fp16 rows ----------------------
__global__ void dot_kernel(const int* __restrict__ ps1, const int* __restrict__ pd1,
                           const int* __restrict__ ps2, const int* __restrict__ pd2,
                           float* __restrict__ out) {
    int t = blockIdx.x * blockDim.x + threadIdx.x;
    int e = t >> 3;
    int l = t & 7;
    if (e >= 2*NP) return;
    const uint4* uf; int s, d;
    if (e < NP) { uf = d_ufh1; s = __ldg(&ps1[e]); d = __ldg(&pd1[e]); }
    else { int e2 = e - NP; uf = d_ufh2; s = __ldg(&ps2[e2]); d = __ldg(&pd2[e2]); }
    uint4 A = __ldg(&uf[s*8 + l]);
    uint4 B = __ldg(&d_ihh[d*8 + l]);
    const __half2* ha = (const __half2*)&A;
    const __half2* hb = (const __half2*)&B;
    float v = 0.f;
    #pragma unroll
    for (int k = 0; k < 4; k++) {
        float2 f = __half22float2(__hmul2(ha[k], hb[k]));
        v += f.x + f.y;
    }
    v += __shfl_xor_sync(0xffffffffu, v, 4);
    v += __shfl_xor_sync(0xffffffffu, v, 2);
    v += __shfl_xor_sync(0xffffffffu, v, 1);
    if (l == 0) out[e] = v;
}

// ---------------- host ------------------------------------------------------
extern "C" void kernel_launch(void* const* d_in, const int* in_sizes, int n_in,
                              void* d_out, int out_size) {
    const float* cf1 = (const float*)d_in[0];
    const float* cf2 = (const float*)d_in[1];
    const float* gf  = (const float*)d_in[2];
    const float* Wm  = (const float*)d_in[3];
    const float* bb  = (const float*)d_in[4];
    const float* gam = (const float*)d_in[5];
    const float* bet = (const float*)d_in[6];
    const float* mu  = (const float*)d_in[7];
    const float* var = (const float*)d_in[8];
    const int* es1 = (const int*)d_in[9];
    const int* ed1 = (const int*)d_in[10];
    const int* es2 = (const int*)d_in[11];
    const int* ed2 = (const int*)d_in[12];
    const int* ps1 = (const int*)d_in[13];
    const int* pd1 = (const int*)d_in[14];
    const int* ps2 = (const int*)d_in[15];
    const int* pd2 = (const int*)d_in[16];
    float* out = (float*)d_out;

    zero_kernel<<<(NC + 255)/256, 256>>>();
    hist_kernel<<<(NE/4 + 255)/256, 256>>>((const int4*)es1, (const int4*)ed1,
                                           (const int4*)es2, (const int4*)ed2);
    prep_kernel<<<(NC + 255)/256, 256>>>();
    build_init_kernel<<<SCAT_B + INIT_B, 256>>>((const int4*)es1, (const int4*)ed1,
                                                (const int4*)es2, (const int4*)ed2,
                                                (const float4*)cf1, (const float4*)cf2,
                                                (const float4*)gf);

    layer_kernel<<<NGB + NCB, 256>>>(0);
    layer_kernel<<<NGB + NCB, 256>>>(1);

    emb_kernel<<<dim3((NC + 63)/64, 2), 128>>>(Wm, bb, gam, bet, mu, var);
    dot_kernel<<<(2*NP*8 + 255)/256, 256>>>(ps1, pd1, ps2, pd2, out);
}